// round 1
// baseline (speedup 1.0000x reference)
#include <cuda_runtime.h>
#include <math.h>

// ---------------- problem constants ----------------
#define B_    4
#define S_    2048
#define D_    1024
#define H_    16
#define DH    64
#define DHR   32
#define DLAT  512
#define MS    (B_*S_)        // 8192 rows
#define DQK   96             // d_h + d_hr

// ---------------- scratch (device globals; no allocation allowed) ----------
__device__ float g_cQ  [MS*DLAT];      // 16 MB
__device__ float g_cKV [MS*DLAT];      // 16 MB
__device__ float g_qC  [MS*D_];        // 32 MB
__device__ float g_qR  [MS*(H_*DHR)];  // 16 MB
__device__ float g_kC  [MS*D_];        // 32 MB
__device__ float g_v   [MS*D_];        // 32 MB  [B,S,H*64]
__device__ float g_kR  [MS*DHR];       // 1 MB
__device__ float g_q   [(size_t)B_*H_*S_*DQK];  // 48 MB [B,H,S,96]
__device__ float g_k   [(size_t)B_*H_*S_*DQK];  // 48 MB
__device__ float g_attn[MS*D_];        // 32 MB  [B,S,H*64]

// ---------------- generic NT SGEMM: C[M,N] = A[M,K] * B[N,K]^T -------------
#define BM 128
#define BN 128
#define BKG 16
#define TM 8
#define TN 8

__global__ __launch_bounds__(256) void sgemm_nt(
    const float* __restrict__ A, const float* __restrict__ Bm,
    float* __restrict__ C, int M, int N, int K)
{
    __shared__ float As[BKG][BM];
    __shared__ float Bs[BKG][BN];

    const int tid = threadIdx.x;
    const int bm  = blockIdx.y * BM;
    const int bn  = blockIdx.x * BN;
    const int tr  = tid / 16;         // 0..15
    const int tc  = tid % 16;         // 0..15
    const int lr  = tid / 4;          // 0..63 (load row)
    const int lc  = (tid % 4) * 4;    // 0,4,8,12 (load col-of-4)

    float acc[TM][TN];
    #pragma unroll
    for (int i = 0; i < TM; i++)
        #pragma unroll
        for (int j = 0; j < TN; j++) acc[i][j] = 0.f;

    for (int k0 = 0; k0 < K; k0 += BKG) {
        #pragma unroll
        for (int p = 0; p < 2; p++) {
            int row = lr + p * 64;
            float4 va = *(const float4*)&A[(size_t)(bm + row) * K + k0 + lc];
            As[lc + 0][row] = va.x; As[lc + 1][row] = va.y;
            As[lc + 2][row] = va.z; As[lc + 3][row] = va.w;
        }
        #pragma unroll
        for (int p = 0; p < 2; p++) {
            int row = lr + p * 64;   // n index
            float4 vb = make_float4(0.f, 0.f, 0.f, 0.f);
            if (bn + row < N)
                vb = *(const float4*)&Bm[(size_t)(bn + row) * K + k0 + lc];
            Bs[lc + 0][row] = vb.x; Bs[lc + 1][row] = vb.y;
            Bs[lc + 2][row] = vb.z; Bs[lc + 3][row] = vb.w;
        }
        __syncthreads();

        #pragma unroll
        for (int kk = 0; kk < BKG; kk++) {
            float ra[TM], rb[TN];
            #pragma unroll
            for (int i = 0; i < TM; i++) ra[i] = As[kk][tr * TM + i];
            #pragma unroll
            for (int j = 0; j < TN; j++) rb[j] = Bs[kk][tc * TN + j];
            #pragma unroll
            for (int i = 0; i < TM; i++)
                #pragma unroll
                for (int j = 0; j < TN; j++)
                    acc[i][j] += ra[i] * rb[j];
        }
        __syncthreads();
    }

    #pragma unroll
    for (int i = 0; i < TM; i++) {
        int row = bm + tr * TM + i;
        #pragma unroll
        for (int j = 0; j < TN; j += 4) {
            int col = bn + tc * TN + j;
            if (col < N)
                *(float4*)&C[(size_t)row * N + col] =
                    make_float4(acc[i][j], acc[i][j+1], acc[i][j+2], acc[i][j+3]);
        }
    }
}

// ---------------- assemble q/k with RoPE -----------------------------------
// grid.x covers (b,h,s) rows, 4 rows per block; grid.y: 0 = q, 1 = k
__global__ __launch_bounds__(256) void assemble_qk(
    const float* __restrict__ qc, const float* __restrict__ qr,
    const float* __restrict__ kc, const float* __restrict__ kr)
{
    const int sub = threadIdx.x >> 6;       // 0..3
    const int t   = threadIdx.x & 63;       // 0..63
    const int idx = blockIdx.x * 4 + sub;   // ((b*H + h)*S + s)
    const int s = idx % S_;
    const int h = (idx / S_) % H_;
    const int b = idx / (S_ * H_);
    const bool isK = (blockIdx.y != 0);

    const size_t bs = (size_t)(b * S_ + s);
    float* dst = (isK ? g_k : g_q) + (size_t)idx * DQK;

    // copy the d_h=64 "C" part
    const float* Cpart = isK ? kc : qc;
    dst[t] = Cpart[bs * D_ + h * DH + t];

    // RoPE on the d_hr=32 part (16 pairs)
    if (t < 16) {
        float x1, x2;
        if (isK) {
            x1 = kr[bs * DHR + 2 * t];
            x2 = kr[bs * DHR + 2 * t + 1];
        } else {
            x1 = qr[bs * (H_ * DHR) + h * DHR + 2 * t];
            x2 = qr[bs * (H_ * DHR) + h * DHR + 2 * t + 1];
        }
        double inv = pow(10000.0, -(double)(2 * t) / (double)DHR);
        double ang = (double)s * inv;
        float c  = (float)cos(ang);
        float sn = (float)sin(ang);
        dst[DH + 2 * t]     = x1 * c  - x2 * sn;
        dst[DH + 2 * t + 1] = x1 * sn + x2 * c;
    }
}

// ---------------- causal flash attention -----------------------------------
// Q,K: [B*H, S, 96]; V,O: [B, S, H*64]. 128 threads, 32x32 tiles.
#define BQ  32
#define BKK 32
#define NEGINF (-1e30f)

__global__ __launch_bounds__(128) void flash_attn(
    const float* __restrict__ Q, const float* __restrict__ Kt,
    const float* __restrict__ V, float* __restrict__ O)
{
    __shared__ float Qs[BQ ][97];
    __shared__ float Ks[BKK][97];
    __shared__ float Vs[BKK][64];
    __shared__ float Ps[BQ ][33];

    const int bh  = blockIdx.y;
    const int b   = bh / H_;
    const int h   = bh % H_;
    const int q0  = blockIdx.x * BQ;
    const int tid = threadIdx.x;
    const int ty  = tid >> 3;      // 0..15 -> rows {2ty, 2ty+1}
    const int tx  = tid & 7;       // 0..7  -> score cols {4tx..4tx+3}, acc cols {8tx..8tx+7}

    // load Q tile (32x96)
    const float* Qbase = Q + ((size_t)bh * S_ + q0) * DQK;
    for (int i = tid; i < BQ * DQK; i += 128) {
        int r = i / DQK, c = i % DQK;
        Qs[r][c] = Qbase[(size_t)r * DQK + c];
    }

    float acc[2][8];
    #pragma unroll
    for (int i = 0; i < 2; i++)
        #pragma unroll
        for (int j = 0; j < 8; j++) acc[i][j] = 0.f;
    float m_i[2] = {NEGINF, NEGINF};
    float l_i[2] = {0.f, 0.f};
    const float scale = rsqrtf(96.f);

    const int nkb = blockIdx.x + 1;   // key tiles 0..q0/32
    for (int kb = 0; kb < nkb; kb++) {
        const int k0 = kb * BKK;
        const float* Kbase = Kt + ((size_t)bh * S_ + k0) * DQK;
        for (int i = tid; i < BKK * DQK; i += 128) {
            int r = i / DQK, c = i % DQK;
            Ks[r][c] = Kbase[(size_t)r * DQK + c];
        }
        for (int i = tid; i < BKK * 64; i += 128) {
            int r = i / 64, c = i % 64;
            Vs[r][c] = V[(size_t)(b * S_ + k0 + r) * D_ + h * DH + c];
        }
        __syncthreads();

        // S = Q K^T  (2 rows x 4 cols per thread)
        float sc[2][4];
        #pragma unroll
        for (int i = 0; i < 2; i++)
            #pragma unroll
            for (int j = 0; j < 4; j++) sc[i][j] = 0.f;
        #pragma unroll 4
        for (int d = 0; d < DQK; d++) {
            float qv0 = Qs[2 * ty][d];
            float qv1 = Qs[2 * ty + 1][d];
            #pragma unroll
            for (int j = 0; j < 4; j++) {
                float kv = Ks[4 * tx + j][d];
                sc[0][j] += qv0 * kv;
                sc[1][j] += qv1 * kv;
            }
        }
        // clamp(+-80) BEFORE scaling, causal mask
        #pragma unroll
        for (int i = 0; i < 2; i++) {
            int qi = q0 + 2 * ty + i;
            #pragma unroll
            for (int j = 0; j < 4; j++) {
                int ki = k0 + 4 * tx + j;
                float val = fminf(fmaxf(sc[i][j], -80.f), 80.f) * scale;
                sc[i][j] = (ki <= qi) ? val : NEGINF;
            }
        }
        // online softmax update
        #pragma unroll
        for (int i = 0; i < 2; i++) {
            float mt = fmaxf(fmaxf(sc[i][0], sc[i][1]), fmaxf(sc[i][2], sc[i][3]));
            #pragma unroll
            for (int off = 4; off >= 1; off >>= 1)
                mt = fmaxf(mt, __shfl_xor_sync(0xffffffffu, mt, off, 8));
            float mnew = fmaxf(m_i[i], mt);
            float p0 = __expf(sc[i][0] - mnew);
            float p1 = __expf(sc[i][1] - mnew);
            float p2 = __expf(sc[i][2] - mnew);
            float p3 = __expf(sc[i][3] - mnew);
            float srow = (p0 + p1) + (p2 + p3);
            #pragma unroll
            for (int off = 4; off >= 1; off >>= 1)
                srow += __shfl_xor_sync(0xffffffffu, srow, off, 8);
            float corr = __expf(m_i[i] - mnew);
            l_i[i] = l_i[i] * corr + srow;
            m_i[i] = mnew;
            #pragma unroll
            for (int j = 0; j < 8; j++) acc[i][j] *= corr;
            Ps[2 * ty + i][4 * tx + 0] = p0;
            Ps[2 * ty + i][4 * tx + 1] = p1;
            Ps[2 * ty + i][4 * tx + 2] = p2;
            Ps[2 * ty + i][4 * tx + 3] = p3;
        }
        __syncthreads();

        // acc += P @ V (2 rows x 8 cols per thread)
        for (int k = 0; k < BKK; k++) {
            float p0 = Ps[2 * ty][k];
            float p1 = Ps[2 * ty + 1][k];
            #pragma unroll
            for (int j = 0; j < 8; j++) {
                float vv = Vs[k][8 * tx + j];
                acc[0][j] += p0 * vv;
                acc[1][j] += p1 * vv;
            }
        }
        __syncthreads();
    }

    #pragma unroll
    for (int i = 0; i < 2; i++) {
        int qi = q0 + 2 * ty + i;
        float inv_l = 1.f / l_i[i];
        #pragma unroll
        for (int j = 0; j < 8; j++)
            O[(size_t)(b * S_ + qi) * D_ + h * DH + 8 * tx + j] = acc[i][j] * inv_l;
    }
}

// ---------------- launch ----------------------------------------------------
extern "C" void kernel_launch(void* const* d_in, const int* in_sizes, int n_in,
                              void* d_out, int out_size)
{
    const float* x     = (const float*)d_in[0];
    const float* W_DQ  = (const float*)d_in[1];
    const float* W_UQ  = (const float*)d_in[2];
    const float* W_QR  = (const float*)d_in[3];
    const float* W_DKV = (const float*)d_in[4];
    const float* W_UK  = (const float*)d_in[5];
    const float* W_UV  = (const float*)d_in[6];
    const float* W_KR  = (const float*)d_in[7];
    const float* W_O   = (const float*)d_in[8];
    float* out = (float*)d_out;

    float *cQ, *cKV, *qC, *qR, *kC, *v, *kR, *q, *k, *attn;
    cudaGetSymbolAddress((void**)&cQ,  g_cQ);
    cudaGetSymbolAddress((void**)&cKV, g_cKV);
    cudaGetSymbolAddress((void**)&qC,  g_qC);
    cudaGetSymbolAddress((void**)&qR,  g_qR);
    cudaGetSymbolAddress((void**)&kC,  g_kC);
    cudaGetSymbolAddress((void**)&v,   g_v);
    cudaGetSymbolAddress((void**)&kR,  g_kR);
    cudaGetSymbolAddress((void**)&q,   g_q);
    cudaGetSymbolAddress((void**)&k,   g_k);
    cudaGetSymbolAddress((void**)&attn,g_attn);

    dim3 blk(256);
    // down / rope projections from x
    sgemm_nt<<<dim3((DLAT + BN - 1) / BN, MS / BM), blk>>>(x, W_DQ,  cQ,  MS, DLAT, D_);
    sgemm_nt<<<dim3((DLAT + BN - 1) / BN, MS / BM), blk>>>(x, W_DKV, cKV, MS, DLAT, D_);
    sgemm_nt<<<dim3(1,                   MS / BM), blk>>>(x, W_KR,  kR,  MS, DHR,  D_);
    // up projections
    sgemm_nt<<<dim3((D_   + BN - 1) / BN, MS / BM), blk>>>(cQ,  W_UQ, qC, MS, D_,        DLAT);
    sgemm_nt<<<dim3((H_*DHR + BN - 1) / BN, MS / BM), blk>>>(cQ,  W_QR, qR, MS, H_ * DHR, DLAT);
    sgemm_nt<<<dim3((D_   + BN - 1) / BN, MS / BM), blk>>>(cKV, W_UK, kC, MS, D_,        DLAT);
    sgemm_nt<<<dim3((D_   + BN - 1) / BN, MS / BM), blk>>>(cKV, W_UV, v,  MS, D_,        DLAT);
    // assemble q/k with rope
    assemble_qk<<<dim3(B_ * H_ * S_ / 4, 2), dim3(256)>>>(qC, qR, kC, kR);
    // causal flash attention
    flash_attn<<<dim3(S_ / BQ, B_ * H_), dim3(128)>>>(q, k, v, attn);
    // output projection
    sgemm_nt<<<dim3((D_ + BN - 1) / BN, MS / BM), blk>>>(attn, W_O, out, MS, D_, D_);
}

// round 2
// speedup vs baseline: 1.2663x; 1.2663x over previous
#include <cuda_runtime.h>
#include <math.h>

// ---------------- problem constants ----------------
#define B_    4
#define S_    2048
#define D_    1024
#define H_    16
#define DH    64
#define DHR   32
#define DLAT  512
#define MS    (B_*S_)        // 8192 rows
#define DQK   96             // d_h + d_hr

typedef unsigned long long ull;

// ---------------- f32x2 packed-math helpers (FFMA2 path) -------------------
__device__ __forceinline__ ull pk2(float lo, float hi) {
    ull r; asm("mov.b64 %0, {%1, %2};" : "=l"(r) : "f"(lo), "f"(hi)); return r;
}
__device__ __forceinline__ void upk2(ull v, float& lo, float& hi) {
    asm("mov.b64 {%0, %1}, %2;" : "=f"(lo), "=f"(hi) : "l"(v));
}
__device__ __forceinline__ ull ffma2(ull a, ull b, ull c) {
    ull d; asm("fma.rn.f32x2 %0, %1, %2, %3;" : "=l"(d) : "l"(a), "l"(b), "l"(c)); return d;
}
__device__ __forceinline__ ull fmul2(ull a, ull b) {
    ull d; asm("mul.rn.f32x2 %0, %1, %2;" : "=l"(d) : "l"(a), "l"(b)); return d;
}

// ---------------- scratch (device globals; no allocation allowed) ----------
__device__ float g_cQ  [MS*DLAT];
__device__ float g_cKV [MS*DLAT];
__device__ float g_qC  [MS*D_];
__device__ float g_qR  [MS*(H_*DHR)];
__device__ float g_kC  [MS*D_];
__device__ float g_v   [MS*D_];        // [B,S,H*64]
__device__ float g_kR  [MS*DHR];
__device__ float g_q   [(size_t)B_*H_*S_*DQK];  // [B,H,S,96]
__device__ float g_k   [(size_t)B_*H_*S_*DQK];
__device__ float g_attn[MS*D_];        // [B,S,H*64]

// ---------------- generic NT SGEMM: C[M,N] = A[M,K] * B[N,K]^T -------------
// 128x128 tile, 256 threads, 8x8 micro-tile, f32x2 packed FMA inner loop.
#define BM 128
#define BN 128
#define BKG 16
#define TM 8

__global__ __launch_bounds__(256) void sgemm_nt(
    const float* __restrict__ A, const float* __restrict__ Bm,
    float* __restrict__ C, int M, int N, int K)
{
    __shared__ float As[BKG][BM];
    __shared__ float Bs[BKG][BN];

    const int tid = threadIdx.x;
    const int bm  = blockIdx.y * BM;
    const int bn  = blockIdx.x * BN;
    const int tr  = tid / 16;         // 0..15 -> rows tr*8..tr*8+7
    const int tc  = tid % 16;         // 0..15 -> cols {tc*4..+3} and {64+tc*4..+3}
    const int lr  = tid / 4;          // 0..63 (tile-load row)
    const int lc  = (tid % 4) * 4;    // 0,4,8,12

    ull acc2[TM][4];
    #pragma unroll
    for (int i = 0; i < TM; i++)
        #pragma unroll
        for (int j = 0; j < 4; j++) acc2[i][j] = 0ull;

    for (int k0 = 0; k0 < K; k0 += BKG) {
        #pragma unroll
        for (int p = 0; p < 2; p++) {
            int row = lr + p * 64;
            float4 va = *(const float4*)&A[(size_t)(bm + row) * K + k0 + lc];
            As[lc + 0][row] = va.x; As[lc + 1][row] = va.y;
            As[lc + 2][row] = va.z; As[lc + 3][row] = va.w;
        }
        #pragma unroll
        for (int p = 0; p < 2; p++) {
            int row = lr + p * 64;   // n index
            float4 vb = make_float4(0.f, 0.f, 0.f, 0.f);
            if (bn + row < N)
                vb = *(const float4*)&Bm[(size_t)(bn + row) * K + k0 + lc];
            Bs[lc + 0][row] = vb.x; Bs[lc + 1][row] = vb.y;
            Bs[lc + 2][row] = vb.z; Bs[lc + 3][row] = vb.w;
        }
        __syncthreads();

        #pragma unroll
        for (int kk = 0; kk < BKG; kk++) {
            float4 a0 = *(const float4*)&As[kk][tr * 8];
            float4 a1 = *(const float4*)&As[kk][tr * 8 + 4];
            float4 b0 = *(const float4*)&Bs[kk][tc * 4];
            float4 b1 = *(const float4*)&Bs[kk][64 + tc * 4];
            ull bb[4];
            bb[0] = pk2(b0.x, b0.y); bb[1] = pk2(b0.z, b0.w);
            bb[2] = pk2(b1.x, b1.y); bb[3] = pk2(b1.z, b1.w);
            float as[8] = {a0.x, a0.y, a0.z, a0.w, a1.x, a1.y, a1.z, a1.w};
            #pragma unroll
            for (int i = 0; i < TM; i++) {
                ull aa = pk2(as[i], as[i]);
                #pragma unroll
                for (int j = 0; j < 4; j++)
                    acc2[i][j] = ffma2(aa, bb[j], acc2[i][j]);
            }
        }
        __syncthreads();
    }

    #pragma unroll
    for (int i = 0; i < TM; i++) {
        int row = bm + tr * 8 + i;
        float o[8];
        #pragma unroll
        for (int j = 0; j < 4; j++) upk2(acc2[i][j], o[2 * j], o[2 * j + 1]);
        int c0 = bn + tc * 4;
        int c1 = bn + 64 + tc * 4;
        if (c0 < N) *(float4*)&C[(size_t)row * N + c0] = make_float4(o[0], o[1], o[2], o[3]);
        if (c1 < N) *(float4*)&C[(size_t)row * N + c1] = make_float4(o[4], o[5], o[6], o[7]);
    }
}

// ---------------- assemble q/k with RoPE -----------------------------------
__global__ __launch_bounds__(256) void assemble_qk(
    const float* __restrict__ qc, const float* __restrict__ qr,
    const float* __restrict__ kc, const float* __restrict__ kr)
{
    const int sub = threadIdx.x >> 6;       // 0..3
    const int t   = threadIdx.x & 63;       // 0..63
    const int idx = blockIdx.x * 4 + sub;   // ((b*H + h)*S + s)
    const int s = idx % S_;
    const int h = (idx / S_) % H_;
    const int b = idx / (S_ * H_);
    const bool isK = (blockIdx.y != 0);

    const size_t bs = (size_t)(b * S_ + s);
    float* dst = (isK ? g_k : g_q) + (size_t)idx * DQK;

    const float* Cpart = isK ? kc : qc;
    dst[t] = Cpart[bs * D_ + h * DH + t];

    if (t < 16) {
        float x1, x2;
        if (isK) {
            x1 = kr[bs * DHR + 2 * t];
            x2 = kr[bs * DHR + 2 * t + 1];
        } else {
            x1 = qr[bs * (H_ * DHR) + h * DHR + 2 * t];
            x2 = qr[bs * (H_ * DHR) + h * DHR + 2 * t + 1];
        }
        double inv = pow(10000.0, -(double)(2 * t) / (double)DHR);
        double ang = (double)s * inv;
        float c  = (float)cos(ang);
        float sn = (float)sin(ang);
        dst[DH + 2 * t]     = x1 * c  - x2 * sn;
        dst[DH + 2 * t + 1] = x1 * sn + x2 * c;
    }
}

// ---------------- causal flash attention (64x64 tiles, f32x2) --------------
// Q,K: [B*H, S, 96]; V,O: [B, S, H*64].
#define BQ  64
#define BKK 64
#define QK_PAD 68
#define NEGINF (-1e30f)

// dynamic smem layout (floats):
//   Qs[96][68]  at 0
//   Ks[96][68]  at 96*68
//   Vs[64][64]  at 2*96*68
//   Ps[64][68]  at 2*96*68 + 64*64        (Ps[col][row])
#define FLASH_SMEM_FLOATS (2*96*QK_PAD + 64*64 + 64*QK_PAD)

__global__ __launch_bounds__(256, 2) void flash_attn(
    const float* __restrict__ Q, const float* __restrict__ Kt,
    const float* __restrict__ V, float* __restrict__ O)
{
    extern __shared__ float sm[];
    float (*Qs)[QK_PAD] = (float(*)[QK_PAD])sm;
    float (*Ks)[QK_PAD] = (float(*)[QK_PAD])(sm + 96 * QK_PAD);
    float (*Vs)[64]     = (float(*)[64])(sm + 2 * 96 * QK_PAD);
    float (*Ps)[QK_PAD] = (float(*)[QK_PAD])(sm + 2 * 96 * QK_PAD + 64 * 64);

    const int bh  = blockIdx.y;
    const int b   = bh / H_;
    const int h   = bh % H_;
    const int q0  = blockIdx.x * BQ;
    const int tid = threadIdx.x;
    const int ty  = tid >> 4;      // 0..15 -> q rows 4ty..4ty+3
    const int tx  = tid & 15;      // 0..15 -> score cols / v cols 4tx..4tx+3

    // load Q tile transposed: Qs[d][row]
    const float* Qbase = Q + ((size_t)bh * S_ + q0) * DQK;
    #pragma unroll 4
    for (int i = tid; i < BQ * DQK; i += 256) {
        int r = i / DQK, c = i % DQK;
        Qs[c][r] = Qbase[(size_t)r * DQK + c];
    }

    ull acc2[4][2];
    #pragma unroll
    for (int i = 0; i < 4; i++) { acc2[i][0] = 0ull; acc2[i][1] = 0ull; }
    float m_i[4] = {NEGINF, NEGINF, NEGINF, NEGINF};
    float l_i[4] = {0.f, 0.f, 0.f, 0.f};
    const float scale = rsqrtf(96.f);

    const int nkb = blockIdx.x + 1;
    for (int kb = 0; kb < nkb; kb++) {
        const int k0 = kb * BKK;
        // load K tile transposed: Ks[d][col]
        const float* Kbase = Kt + ((size_t)bh * S_ + k0) * DQK;
        #pragma unroll 4
        for (int i = tid; i < BKK * DQK; i += 256) {
            int r = i / DQK, c = i % DQK;
            Ks[c][r] = Kbase[(size_t)r * DQK + c];
        }
        // load V tile: Vs[k][c] (row-major, float4)
        #pragma unroll
        for (int i = tid; i < BKK * 16; i += 256) {
            int r = i / 16, c4 = (i % 16) * 4;
            *(float4*)&Vs[r][c4] =
                *(const float4*)&V[(size_t)(b * S_ + k0 + r) * D_ + h * DH + c4];
        }
        __syncthreads();

        // ---- S = Q K^T ----
        ull sc2[4][2];
        #pragma unroll
        for (int i = 0; i < 4; i++) { sc2[i][0] = 0ull; sc2[i][1] = 0ull; }
        #pragma unroll 4
        for (int d = 0; d < DQK; d++) {
            float4 q4 = *(const float4*)&Qs[d][ty * 4];
            ull k01 = *(const ull*)&Ks[d][tx * 4];
            ull k23 = *(const ull*)&Ks[d][tx * 4 + 2];
            ull qq;
            qq = pk2(q4.x, q4.x);
            sc2[0][0] = ffma2(qq, k01, sc2[0][0]); sc2[0][1] = ffma2(qq, k23, sc2[0][1]);
            qq = pk2(q4.y, q4.y);
            sc2[1][0] = ffma2(qq, k01, sc2[1][0]); sc2[1][1] = ffma2(qq, k23, sc2[1][1]);
            qq = pk2(q4.z, q4.z);
            sc2[2][0] = ffma2(qq, k01, sc2[2][0]); sc2[2][1] = ffma2(qq, k23, sc2[2][1]);
            qq = pk2(q4.w, q4.w);
            sc2[3][0] = ffma2(qq, k01, sc2[3][0]); sc2[3][1] = ffma2(qq, k23, sc2[3][1]);
        }

        // ---- clamp, scale, mask, online softmax ----
        #pragma unroll
        for (int i = 0; i < 4; i++) {
            float s0, s1, s2, s3;
            upk2(sc2[i][0], s0, s1);
            upk2(sc2[i][1], s2, s3);
            const int qi = q0 + 4 * ty + i;
            const int kc = k0 + 4 * tx;
            s0 = (kc + 0 <= qi) ? fminf(fmaxf(s0, -80.f), 80.f) * scale : NEGINF;
            s1 = (kc + 1 <= qi) ? fminf(fmaxf(s1, -80.f), 80.f) * scale : NEGINF;
            s2 = (kc + 2 <= qi) ? fminf(fmaxf(s2, -80.f), 80.f) * scale : NEGINF;
            s3 = (kc + 3 <= qi) ? fminf(fmaxf(s3, -80.f), 80.f) * scale : NEGINF;

            float mt = fmaxf(fmaxf(s0, s1), fmaxf(s2, s3));
            #pragma unroll
            for (int off = 8; off >= 1; off >>= 1)
                mt = fmaxf(mt, __shfl_xor_sync(0xffffffffu, mt, off));
            float mnew = fmaxf(m_i[i], mt);
            float p0 = __expf(s0 - mnew);
            float p1 = __expf(s1 - mnew);
            float p2 = __expf(s2 - mnew);
            float p3 = __expf(s3 - mnew);
            float srow = (p0 + p1) + (p2 + p3);
            #pragma unroll
            for (int off = 8; off >= 1; off >>= 1)
                srow += __shfl_xor_sync(0xffffffffu, srow, off);
            float corr = __expf(m_i[i] - mnew);
            l_i[i] = l_i[i] * corr + srow;
            m_i[i] = mnew;
            ull cc = pk2(corr, corr);
            acc2[i][0] = fmul2(acc2[i][0], cc);
            acc2[i][1] = fmul2(acc2[i][1], cc);
            // store P transposed: Ps[col][row]
            Ps[4 * tx + 0][4 * ty + i] = p0;
            Ps[4 * tx + 1][4 * ty + i] = p1;
            Ps[4 * tx + 2][4 * ty + i] = p2;
            Ps[4 * tx + 3][4 * ty + i] = p3;
        }
        __syncthreads();

        // ---- acc += P @ V ----
        #pragma unroll 4
        for (int k = 0; k < BKK; k++) {
            float4 p4 = *(const float4*)&Ps[k][ty * 4];
            ull v01 = *(const ull*)&Vs[k][tx * 4];
            ull v23 = *(const ull*)&Vs[k][tx * 4 + 2];
            ull pp;
            pp = pk2(p4.x, p4.x);
            acc2[0][0] = ffma2(pp, v01, acc2[0][0]); acc2[0][1] = ffma2(pp, v23, acc2[0][1]);
            pp = pk2(p4.y, p4.y);
            acc2[1][0] = ffma2(pp, v01, acc2[1][0]); acc2[1][1] = ffma2(pp, v23, acc2[1][1]);
            pp = pk2(p4.z, p4.z);
            acc2[2][0] = ffma2(pp, v01, acc2[2][0]); acc2[2][1] = ffma2(pp, v23, acc2[2][1]);
            pp = pk2(p4.w, p4.w);
            acc2[3][0] = ffma2(pp, v01, acc2[3][0]); acc2[3][1] = ffma2(pp, v23, acc2[3][1]);
        }
        __syncthreads();
    }

    #pragma unroll
    for (int i = 0; i < 4; i++) {
        int qi = q0 + 4 * ty + i;
        float inv_l = 1.f / l_i[i];
        float o0, o1, o2, o3;
        upk2(acc2[i][0], o0, o1);
        upk2(acc2[i][1], o2, o3);
        *(float4*)&O[(size_t)(b * S_ + qi) * D_ + h * DH + 4 * tx] =
            make_float4(o0 * inv_l, o1 * inv_l, o2 * inv_l, o3 * inv_l);
    }
}

// ---------------- launch ----------------------------------------------------
extern "C" void kernel_launch(void* const* d_in, const int* in_sizes, int n_in,
                              void* d_out, int out_size)
{
    const float* x     = (const float*)d_in[0];
    const float* W_DQ  = (const float*)d_in[1];
    const float* W_UQ  = (const float*)d_in[2];
    const float* W_QR  = (const float*)d_in[3];
    const float* W_DKV = (const float*)d_in[4];
    const float* W_UK  = (const float*)d_in[5];
    const float* W_UV  = (const float*)d_in[6];
    const float* W_KR  = (const float*)d_in[7];
    const float* W_O   = (const float*)d_in[8];
    float* out = (float*)d_out;

    float *cQ, *cKV, *qC, *qR, *kC, *v, *kR, *q, *k, *attn;
    cudaGetSymbolAddress((void**)&cQ,  g_cQ);
    cudaGetSymbolAddress((void**)&cKV, g_cKV);
    cudaGetSymbolAddress((void**)&qC,  g_qC);
    cudaGetSymbolAddress((void**)&qR,  g_qR);
    cudaGetSymbolAddress((void**)&kC,  g_kC);
    cudaGetSymbolAddress((void**)&v,   g_v);
    cudaGetSymbolAddress((void**)&kR,  g_kR);
    cudaGetSymbolAddress((void**)&q,   g_q);
    cudaGetSymbolAddress((void**)&k,   g_k);
    cudaGetSymbolAddress((void**)&attn,g_attn);

    static int configured = 0;
    if (!configured) {
        cudaFuncSetAttribute(flash_attn, cudaFuncAttributeMaxDynamicSharedMemorySize,
                             FLASH_SMEM_FLOATS * sizeof(float));
        configured = 1;
    }

    dim3 blk(256);
    sgemm_nt<<<dim3((DLAT + BN - 1) / BN, MS / BM), blk>>>(x, W_DQ,  cQ,  MS, DLAT, D_);
    sgemm_nt<<<dim3((DLAT + BN - 1) / BN, MS / BM), blk>>>(x, W_DKV, cKV, MS, DLAT, D_);
    sgemm_nt<<<dim3(1,                   MS / BM), blk>>>(x, W_KR,  kR,  MS, DHR,  D_);
    sgemm_nt<<<dim3((D_   + BN - 1) / BN, MS / BM), blk>>>(cQ,  W_UQ, qC, MS, D_,        DLAT);
    sgemm_nt<<<dim3((H_*DHR + BN - 1) / BN, MS / BM), blk>>>(cQ,  W_QR, qR, MS, H_ * DHR, DLAT);
    sgemm_nt<<<dim3((D_   + BN - 1) / BN, MS / BM), blk>>>(cKV, W_UK, kC, MS, D_,        DLAT);
    sgemm_nt<<<dim3((D_   + BN - 1) / BN, MS / BM), blk>>>(cKV, W_UV, v,  MS, D_,        DLAT);
    assemble_qk<<<dim3(B_ * H_ * S_ / 4, 2), dim3(256)>>>(qC, qR, kC, kR);
    flash_attn<<<dim3(S_ / BQ, B_ * H_), dim3(256), FLASH_SMEM_FLOATS * sizeof(float)>>>(q, k, v, attn);
    sgemm_nt<<<dim3((D_ + BN - 1) / BN, MS / BM), blk>>>(attn, W_O, out, MS, D_, D_);
}

// round 3
// speedup vs baseline: 1.7036x; 1.3453x over previous
#include <cuda_runtime.h>
#include <cuda_bf16.h>
#include <math.h>
#include <stdint.h>

// ---------------- problem constants ----------------
#define B_    4
#define S_    2048
#define D_    1024
#define H_    16
#define DH    64
#define DHR   32
#define DLAT  512
#define MS    (B_*S_)
#define DQK   96

typedef uint32_t u32;
typedef unsigned short u16;

// ---------------- weight pack offsets (elements) ----------------
#define OFF_DQ   0
#define OFF_UQ   524288
#define OFF_QR   1048576
#define OFF_DKV  1310720
#define OFF_UK   1835008
#define OFF_UV   2359296
#define OFF_KR   2883584
#define OFF_WO   2916352
#define WTOT     3964928

// ---------------- scratch (device globals; no allocation) -------
__device__ __align__(16) u16 g_xh [MS*D_],  g_xl [MS*D_];
__device__ __align__(16) u16 g_wh [WTOT],   g_wl [WTOT];
__device__ __align__(16) u16 g_cQh[MS*DLAT],g_cQl[MS*DLAT];
__device__ __align__(16) u16 g_cKVh[MS*DLAT],g_cKVl[MS*DLAT];
__device__ __align__(16) float g_qC[MS*D_];
__device__ __align__(16) float g_qR[MS*H_*DHR];
__device__ __align__(16) float g_kC[MS*D_];
__device__ __align__(16) float g_kR[MS*DHR];
__device__ __align__(16) u16 g_vh [MS*D_],  g_vl [MS*D_];
__device__ __align__(16) u16 g_qh [(size_t)B_*H_*S_*DQK], g_ql[(size_t)B_*H_*S_*DQK];
__device__ __align__(16) u16 g_kh [(size_t)B_*H_*S_*DQK], g_kl[(size_t)B_*H_*S_*DQK];
__device__ __align__(16) u16 g_ah [MS*D_],  g_al [MS*D_];

// ---------------- helpers ----------------
__device__ __forceinline__ unsigned sptr(const void* p) {
    return (unsigned)__cvta_generic_to_shared(p);
}
__device__ __forceinline__ void ldmx4(u32* r, unsigned a) {
    asm volatile("ldmatrix.sync.aligned.m8n8.x4.shared.b16 {%0,%1,%2,%3},[%4];"
        : "=r"(r[0]), "=r"(r[1]), "=r"(r[2]), "=r"(r[3]) : "r"(a));
}
__device__ __forceinline__ void ldmx4t(u32* r, unsigned a) {
    asm volatile("ldmatrix.sync.aligned.m8n8.x4.trans.shared.b16 {%0,%1,%2,%3},[%4];"
        : "=r"(r[0]), "=r"(r[1]), "=r"(r[2]), "=r"(r[3]) : "r"(a));
}
__device__ __forceinline__ void mma16816(float* c, const u32* a, u32 b0, u32 b1) {
    asm volatile("mma.sync.aligned.m16n8k16.row.col.f32.bf16.bf16.f32 "
        "{%0,%1,%2,%3},{%4,%5,%6,%7},{%8,%9},{%0,%1,%2,%3};"
        : "+f"(c[0]), "+f"(c[1]), "+f"(c[2]), "+f"(c[3])
        : "r"(a[0]), "r"(a[1]), "r"(a[2]), "r"(a[3]), "r"(b0), "r"(b1));
}
// split float pair into packed bf16x2 hi and lo words (elem0 in low half)
__device__ __forceinline__ void split_pack(float a, float b, u32& hi, u32& lo) {
    __nv_bfloat16 ha = __float2bfloat16(a), hb = __float2bfloat16(b);
    __nv_bfloat162 hh; hh.x = ha; hh.y = hb;
    hi = *(u32*)&hh;
    __nv_bfloat162 ll;
    ll.x = __float2bfloat16(a - __bfloat162float(ha));
    ll.y = __float2bfloat16(b - __bfloat162float(hb));
    lo = *(u32*)&ll;
}
__device__ __forceinline__ void wsplit(u16* hp, u16* lp, size_t idx, float v) {
    __nv_bfloat16 h = __float2bfloat16(v);
    hp[idx] = *(u16*)&h;
    __nv_bfloat16 l = __float2bfloat16(v - __bfloat162float(h));
    lp[idx] = *(u16*)&l;
}

// ---------------- fp32 -> bf16 hi/lo split kernel ----------------
__global__ __launch_bounds__(256) void splitk(
    const float* __restrict__ in, u16* __restrict__ hi, u16* __restrict__ lo, int n4)
{
    int i = blockIdx.x * 256 + threadIdx.x;
    if (i >= n4) return;
    float4 v = ((const float4*)in)[i];
    u32 h0, l0, h1, l1;
    split_pack(v.x, v.y, h0, l0);
    split_pack(v.z, v.w, h1, l1);
    ((uint2*)hi)[i] = make_uint2(h0, h1);
    ((uint2*)lo)[i] = make_uint2(l0, l1);
}

// ---------------- split-bf16 GEMM: C[M,N] = A[M,K] * B[N,K]^T ----
// A,B given as bf16 hi/lo. Output: fp32 (Cf) or bf16 hi/lo (Ch/Cl).
#define GBM 128
#define GBN 128
#define GBK 32
#define GP  40    // padded row stride (bf16 elems)

__global__ __launch_bounds__(256) void gemm_bf16s(
    const u16* __restrict__ Ah, const u16* __restrict__ Al,
    const u16* __restrict__ Bh, const u16* __restrict__ Bl,
    float* __restrict__ Cf, u16* __restrict__ Ch, u16* __restrict__ Cl,
    int M, int N, int K)
{
    __shared__ __align__(16) u16 As[2][GBM*GP];
    __shared__ __align__(16) u16 Bs[2][GBM*GP];

    const int tid = threadIdx.x, lane = tid & 31, wid = tid >> 5;
    const int bm = blockIdx.y * GBM, bn = blockIdx.x * GBN;
    const int wm = (wid & 3) * 32, wn = (wid >> 2) * 64;
    const int g = lane >> 2, t = lane & 3;

    float acc[2][8][4];
    #pragma unroll
    for (int mi = 0; mi < 2; mi++)
        #pragma unroll
        for (int nj = 0; nj < 8; nj++)
            #pragma unroll
            for (int c = 0; c < 4; c++) acc[mi][nj][c] = 0.f;

    for (int k0 = 0; k0 < K; k0 += GBK) {
        #pragma unroll
        for (int l = 0; l < 2; l++) {
            int c = tid + l * 256;
            int row = c >> 2, s = (c & 3) * 8;
            size_t ga = (size_t)(bm + row) * K + k0 + s;
            *(uint4*)&As[0][row*GP + s] = *(const uint4*)&Ah[ga];
            *(uint4*)&As[1][row*GP + s] = *(const uint4*)&Al[ga];
            uint4 vh = make_uint4(0,0,0,0), vl = make_uint4(0,0,0,0);
            if (bn + row < N) {
                size_t gb = (size_t)(bn + row) * K + k0 + s;
                vh = *(const uint4*)&Bh[gb];
                vl = *(const uint4*)&Bl[gb];
            }
            *(uint4*)&Bs[0][row*GP + s] = vh;
            *(uint4*)&Bs[1][row*GP + s] = vl;
        }
        __syncthreads();

        #pragma unroll
        for (int kk = 0; kk < GBK; kk += 16) {
            u32 a[2][2][4];
            #pragma unroll
            for (int mi = 0; mi < 2; mi++) {
                int row = wm + mi * 16 + (lane & 15), col = kk + (lane >> 4) * 8;
                ldmx4(a[0][mi], sptr(&As[0][row*GP + col]));
                ldmx4(a[1][mi], sptr(&As[1][row*GP + col]));
            }
            #pragma unroll
            for (int ng = 0; ng < 4; ng++) {
                u32 b0[4], b1[4];
                int row = wn + ng * 16 + (lane & 15), col = kk + (lane >> 4) * 8;
                ldmx4(b0, sptr(&Bs[0][row*GP + col]));
                ldmx4(b1, sptr(&Bs[1][row*GP + col]));
                #pragma unroll
                for (int mi = 0; mi < 2; mi++) {
                    mma16816(acc[mi][2*ng],   a[0][mi], b0[0], b0[2]);
                    mma16816(acc[mi][2*ng],   a[0][mi], b1[0], b1[2]);
                    mma16816(acc[mi][2*ng],   a[1][mi], b0[0], b0[2]);
                    mma16816(acc[mi][2*ng+1], a[0][mi], b0[1], b0[3]);
                    mma16816(acc[mi][2*ng+1], a[0][mi], b1[1], b1[3]);
                    mma16816(acc[mi][2*ng+1], a[1][mi], b0[1], b0[3]);
                }
            }
        }
        __syncthreads();
    }

    #pragma unroll
    for (int mi = 0; mi < 2; mi++) {
        int r0 = bm + wm + mi * 16 + g;
        #pragma unroll
        for (int nj = 0; nj < 8; nj++) {
            int col = bn + wn + nj * 8 + t * 2;
            if (col >= N) continue;
            if (Cf) {
                *(float2*)&Cf[(size_t)r0 * N + col] =
                    make_float2(acc[mi][nj][0], acc[mi][nj][1]);
                *(float2*)&Cf[(size_t)(r0+8) * N + col] =
                    make_float2(acc[mi][nj][2], acc[mi][nj][3]);
            } else {
                u32 h0, l0, h1, l1;
                split_pack(acc[mi][nj][0], acc[mi][nj][1], h0, l0);
                split_pack(acc[mi][nj][2], acc[mi][nj][3], h1, l1);
                *(u32*)&Ch[(size_t)r0 * N + col] = h0;
                *(u32*)&Cl[(size_t)r0 * N + col] = l0;
                *(u32*)&Ch[(size_t)(r0+8) * N + col] = h1;
                *(u32*)&Cl[(size_t)(r0+8) * N + col] = l1;
            }
        }
    }
}

// ---------------- assemble q/k with RoPE -> bf16 hi/lo ----------------
__global__ __launch_bounds__(256) void assemble_qk(
    const float* __restrict__ qc, const float* __restrict__ qr,
    const float* __restrict__ kc, const float* __restrict__ kr,
    u16* __restrict__ qhA, u16* __restrict__ qlA,
    u16* __restrict__ khA, u16* __restrict__ klA)
{
    const int sub = threadIdx.x >> 6;
    const int t   = threadIdx.x & 63;
    const int idx = blockIdx.x * 4 + sub;     // ((b*H + h)*S + s)
    const int s = idx % S_;
    const int h = (idx / S_) % H_;
    const int b = idx / (S_ * H_);
    const bool isK = (blockIdx.y != 0);

    const size_t bs = (size_t)(b * S_ + s);
    u16* hp = isK ? khA : qhA;
    u16* lp = isK ? klA : qlA;
    const size_t base = (size_t)idx * DQK;

    const float* Cpart = isK ? kc : qc;
    wsplit(hp, lp, base + t, Cpart[bs * D_ + h * DH + t]);

    if (t < 16) {
        float x1, x2;
        if (isK) {
            x1 = kr[bs * DHR + 2 * t];
            x2 = kr[bs * DHR + 2 * t + 1];
        } else {
            x1 = qr[bs * (H_ * DHR) + h * DHR + 2 * t];
            x2 = qr[bs * (H_ * DHR) + h * DHR + 2 * t + 1];
        }
        double inv = pow(10000.0, -(double)(2 * t) / (double)DHR);
        double ang = (double)s * inv;
        float c  = (float)cos(ang);
        float sn = (float)sin(ang);
        wsplit(hp, lp, base + DH + 2 * t,     x1 * c  - x2 * sn);
        wsplit(hp, lp, base + DH + 2 * t + 1, x1 * sn + x2 * c);
    }
}

// ---------------- flash attention with split-bf16 MMA ----------------
#define FBQ 64
#define FBK 64
#define QKP 104
#define VP  72
#define FLASH_SMEM_BYTES ((4*64*QKP + 2*64*VP) * 2)

__global__ __launch_bounds__(128) void flash_mma(
    const u16* __restrict__ Qh, const u16* __restrict__ Ql,
    const u16* __restrict__ Kh, const u16* __restrict__ Kl,
    const u16* __restrict__ Vh, const u16* __restrict__ Vl,
    u16* __restrict__ Oh, u16* __restrict__ Ol)
{
    extern __shared__ __align__(16) u16 smf[];
    u16* Qsh = smf;
    u16* Qsl = smf + 64*QKP;
    u16* Ksh = smf + 2*64*QKP;
    u16* Ksl = smf + 3*64*QKP;
    u16* Vsh = smf + 4*64*QKP;
    u16* Vsl = smf + 4*64*QKP + 64*VP;

    const int bh = blockIdx.y, b = bh / H_, h = bh % H_;
    const int q0 = blockIdx.x * FBQ;
    const int tid = threadIdx.x, w = tid >> 5, lane = tid & 31;
    const int g = lane >> 2, t = lane & 3;

    // load Q tile (64 x 96 bf16 hi/lo)
    const size_t qbase = ((size_t)bh * S_ + q0) * DQK;
    for (int c = tid; c < 64 * 12; c += 128) {
        int r = c / 12, s = c % 12;
        *(uint4*)&Qsh[r*QKP + s*8] = *(const uint4*)&Qh[qbase + (size_t)r*DQK + s*8];
        *(uint4*)&Qsl[r*QKP + s*8] = *(const uint4*)&Ql[qbase + (size_t)r*DQK + s*8];
    }

    float acco[8][4];
    #pragma unroll
    for (int j = 0; j < 8; j++)
        #pragma unroll
        for (int c = 0; c < 4; c++) acco[j][c] = 0.f;
    float mstate[2] = {-INFINITY, -INFINITY};
    float lstate[2] = {0.f, 0.f};
    const float scale = rsqrtf(96.f);
    const int qiA = q0 + w * 16 + g;
    const int qiB = qiA + 8;

    const int nkb = blockIdx.x + 1;
    for (int kb = 0; kb < nkb; kb++) {
        const int k0 = kb * FBK;
        const size_t kbase = ((size_t)bh * S_ + k0) * DQK;
        for (int c = tid; c < 64 * 12; c += 128) {
            int r = c / 12, s = c % 12;
            *(uint4*)&Ksh[r*QKP + s*8] = *(const uint4*)&Kh[kbase + (size_t)r*DQK + s*8];
            *(uint4*)&Ksl[r*QKP + s*8] = *(const uint4*)&Kl[kbase + (size_t)r*DQK + s*8];
        }
        for (int c = tid; c < 64 * 8; c += 128) {
            int r = c >> 3, s = c & 7;
            size_t gv = ((size_t)(b * S_ + k0 + r)) * D_ + h * DH + s * 8;
            *(uint4*)&Vsh[r*VP + s*8] = *(const uint4*)&Vh[gv];
            *(uint4*)&Vsl[r*VP + s*8] = *(const uint4*)&Vl[gv];
        }
        __syncthreads();

        // ---- S = Q K^T (split-3) ----
        float sc[8][4];
        #pragma unroll
        for (int j = 0; j < 8; j++)
            #pragma unroll
            for (int c = 0; c < 4; c++) sc[j][c] = 0.f;

        #pragma unroll
        for (int kc = 0; kc < 6; kc++) {
            u32 ah[4], al[4];
            {
                int row = w * 16 + (lane & 15), col = kc * 16 + (lane >> 4) * 8;
                ldmx4(ah, sptr(&Qsh[row*QKP + col]));
                ldmx4(al, sptr(&Qsl[row*QKP + col]));
            }
            #pragma unroll
            for (int ng = 0; ng < 4; ng++) {
                u32 b0[4], b1[4];
                int row = ng * 16 + (lane & 15), col = kc * 16 + (lane >> 4) * 8;
                ldmx4(b0, sptr(&Ksh[row*QKP + col]));
                ldmx4(b1, sptr(&Ksl[row*QKP + col]));
                mma16816(sc[2*ng],   ah, b0[0], b0[2]);
                mma16816(sc[2*ng],   ah, b1[0], b1[2]);
                mma16816(sc[2*ng],   al, b0[0], b0[2]);
                mma16816(sc[2*ng+1], ah, b0[1], b0[3]);
                mma16816(sc[2*ng+1], ah, b1[1], b1[3]);
                mma16816(sc[2*ng+1], al, b0[1], b0[3]);
            }
        }

        // ---- clamp, scale, causal mask ----
        const bool diag = (kb == nkb - 1);
        #pragma unroll
        for (int j = 0; j < 8; j++) {
            int kcol = k0 + j * 8 + t * 2;
            #pragma unroll
            for (int c = 0; c < 4; c++) {
                int ki = kcol + (c & 1);
                int qi = (c < 2) ? qiA : qiB;
                float v = fminf(fmaxf(sc[j][c], -80.f), 80.f) * scale;
                sc[j][c] = (!diag || ki <= qi) ? v : -INFINITY;
            }
        }

        // ---- online softmax ----
        float mA = -INFINITY, mB = -INFINITY;
        #pragma unroll
        for (int j = 0; j < 8; j++) {
            mA = fmaxf(mA, fmaxf(sc[j][0], sc[j][1]));
            mB = fmaxf(mB, fmaxf(sc[j][2], sc[j][3]));
        }
        mA = fmaxf(mA, __shfl_xor_sync(0xffffffffu, mA, 1));
        mA = fmaxf(mA, __shfl_xor_sync(0xffffffffu, mA, 2));
        mB = fmaxf(mB, __shfl_xor_sync(0xffffffffu, mB, 1));
        mB = fmaxf(mB, __shfl_xor_sync(0xffffffffu, mB, 2));
        float mnA = fmaxf(mstate[0], mA), mnB = fmaxf(mstate[1], mB);
        float corrA = __expf(mstate[0] - mnA);
        float corrB = __expf(mstate[1] - mnB);
        float sumA = 0.f, sumB = 0.f;
        #pragma unroll
        for (int j = 0; j < 8; j++) {
            sc[j][0] = __expf(sc[j][0] - mnA); sumA += sc[j][0];
            sc[j][1] = __expf(sc[j][1] - mnA); sumA += sc[j][1];
            sc[j][2] = __expf(sc[j][2] - mnB); sumB += sc[j][2];
            sc[j][3] = __expf(sc[j][3] - mnB); sumB += sc[j][3];
        }
        sumA += __shfl_xor_sync(0xffffffffu, sumA, 1);
        sumA += __shfl_xor_sync(0xffffffffu, sumA, 2);
        sumB += __shfl_xor_sync(0xffffffffu, sumB, 1);
        sumB += __shfl_xor_sync(0xffffffffu, sumB, 2);
        lstate[0] = lstate[0] * corrA + sumA;
        lstate[1] = lstate[1] * corrB + sumB;
        mstate[0] = mnA; mstate[1] = mnB;
        #pragma unroll
        for (int vj = 0; vj < 8; vj++) {
            acco[vj][0] *= corrA; acco[vj][1] *= corrA;
            acco[vj][2] *= corrB; acco[vj][3] *= corrB;
        }

        // ---- acc += P V (split-3, P packed in-register) ----
        #pragma unroll
        for (int kcp = 0; kcp < 4; kcp++) {
            u32 ph[4], pl[4];
            split_pack(sc[2*kcp  ][0], sc[2*kcp  ][1], ph[0], pl[0]);
            split_pack(sc[2*kcp  ][2], sc[2*kcp  ][3], ph[1], pl[1]);
            split_pack(sc[2*kcp+1][0], sc[2*kcp+1][1], ph[2], pl[2]);
            split_pack(sc[2*kcp+1][2], sc[2*kcp+1][3], ph[3], pl[3]);
            #pragma unroll
            for (int vg = 0; vg < 4; vg++) {
                u32 v0[4], v1[4];
                int row = kcp * 16 + (lane & 15), col = vg * 16 + (lane >> 4) * 8;
                ldmx4t(v0, sptr(&Vsh[row*VP + col]));
                ldmx4t(v1, sptr(&Vsl[row*VP + col]));
                mma16816(acco[2*vg],   ph, v0[0], v0[1]);
                mma16816(acco[2*vg],   ph, v1[0], v1[1]);
                mma16816(acco[2*vg],   pl, v0[0], v0[1]);
                mma16816(acco[2*vg+1], ph, v0[2], v0[3]);
                mma16816(acco[2*vg+1], ph, v1[2], v1[3]);
                mma16816(acco[2*vg+1], pl, v0[2], v0[3]);
            }
        }
        __syncthreads();
    }

    // ---- epilogue: normalize, split-write to attn hi/lo ----
    float ilA = 1.f / lstate[0], ilB = 1.f / lstate[1];
    int rA = b * S_ + q0 + w * 16 + g;
    #pragma unroll
    for (int vj = 0; vj < 8; vj++) {
        int col = h * DH + vj * 8 + t * 2;
        u32 h0, l0, h1, l1;
        split_pack(acco[vj][0] * ilA, acco[vj][1] * ilA, h0, l0);
        split_pack(acco[vj][2] * ilB, acco[vj][3] * ilB, h1, l1);
        *(u32*)&Oh[(size_t)rA * D_ + col] = h0;
        *(u32*)&Ol[(size_t)rA * D_ + col] = l0;
        *(u32*)&Oh[(size_t)(rA+8) * D_ + col] = h1;
        *(u32*)&Ol[(size_t)(rA+8) * D_ + col] = l1;
    }
}

// ---------------- launch ----------------
extern "C" void kernel_launch(void* const* d_in, const int* in_sizes, int n_in,
                              void* d_out, int out_size)
{
    const float* x     = (const float*)d_in[0];
    const float* W_DQ  = (const float*)d_in[1];
    const float* W_UQ  = (const float*)d_in[2];
    const float* W_QR  = (const float*)d_in[3];
    const float* W_DKV = (const float*)d_in[4];
    const float* W_UK  = (const float*)d_in[5];
    const float* W_UV  = (const float*)d_in[6];
    const float* W_KR  = (const float*)d_in[7];
    const float* W_O   = (const float*)d_in[8];
    float* out = (float*)d_out;

    u16 *xh,*xl,*wh,*wl,*cQh,*cQl,*cKVh,*cKVl,*vh,*vl,*qh,*ql,*kh,*kl,*ah,*al;
    float *qC,*qR,*kC,*kR;
    cudaGetSymbolAddress((void**)&xh,  g_xh);   cudaGetSymbolAddress((void**)&xl,  g_xl);
    cudaGetSymbolAddress((void**)&wh,  g_wh);   cudaGetSymbolAddress((void**)&wl,  g_wl);
    cudaGetSymbolAddress((void**)&cQh, g_cQh);  cudaGetSymbolAddress((void**)&cQl, g_cQl);
    cudaGetSymbolAddress((void**)&cKVh,g_cKVh); cudaGetSymbolAddress((void**)&cKVl,g_cKVl);
    cudaGetSymbolAddress((void**)&qC,  g_qC);   cudaGetSymbolAddress((void**)&qR,  g_qR);
    cudaGetSymbolAddress((void**)&kC,  g_kC);   cudaGetSymbolAddress((void**)&kR,  g_kR);
    cudaGetSymbolAddress((void**)&vh,  g_vh);   cudaGetSymbolAddress((void**)&vl,  g_vl);
    cudaGetSymbolAddress((void**)&qh,  g_qh);   cudaGetSymbolAddress((void**)&ql,  g_ql);
    cudaGetSymbolAddress((void**)&kh,  g_kh);   cudaGetSymbolAddress((void**)&kl,  g_kl);
    cudaGetSymbolAddress((void**)&ah,  g_ah);   cudaGetSymbolAddress((void**)&al,  g_al);

    static int configured = 0;
    if (!configured) {
        cudaFuncSetAttribute(flash_mma, cudaFuncAttributeMaxDynamicSharedMemorySize,
                             FLASH_SMEM_BYTES);
        configured = 1;
    }

    // ---- split fp32 inputs into bf16 hi/lo ----
    auto spl = [&](const float* src, u16* dh, u16* dl, int n) {
        int n4 = n / 4;
        splitk<<<(n4 + 255) / 256, 256>>>(src, dh, dl, n4);
    };
    spl(x,     xh,          xl,          MS * D_);
    spl(W_DQ,  wh + OFF_DQ,  wl + OFF_DQ,  DLAT * D_);
    spl(W_UQ,  wh + OFF_UQ,  wl + OFF_UQ,  D_ * DLAT);
    spl(W_QR,  wh + OFF_QR,  wl + OFF_QR,  H_ * DHR * DLAT);
    spl(W_DKV, wh + OFF_DKV, wl + OFF_DKV, DLAT * D_);
    spl(W_UK,  wh + OFF_UK,  wl + OFF_UK,  D_ * DLAT);
    spl(W_UV,  wh + OFF_UV,  wl + OFF_UV,  D_ * DLAT);
    spl(W_KR,  wh + OFF_KR,  wl + OFF_KR,  DHR * D_);
    spl(W_O,   wh + OFF_WO,  wl + OFF_WO,  D_ * D_);

    dim3 blk(256);
    auto gemm = [&](const u16* Ahp, const u16* Alp, const u16* Bhp, const u16* Blp,
                    float* Cfp, u16* Chp, u16* Clp, int M, int N, int K) {
        gemm_bf16s<<<dim3((N + GBN - 1) / GBN, M / GBM), blk>>>(
            Ahp, Alp, Bhp, Blp, Cfp, Chp, Clp, M, N, K);
    };

    // down projections
    gemm(xh, xl, wh + OFF_DQ,  wl + OFF_DQ,  nullptr, cQh, cQl, MS, DLAT, D_);
    gemm(xh, xl, wh + OFF_DKV, wl + OFF_DKV, nullptr, cKVh, cKVl, MS, DLAT, D_);
    gemm(xh, xl, wh + OFF_KR,  wl + OFF_KR,  kR, nullptr, nullptr, MS, DHR, D_);
    // up projections
    gemm(cQh,  cQl,  wh + OFF_UQ, wl + OFF_UQ, qC, nullptr, nullptr, MS, D_, DLAT);
    gemm(cQh,  cQl,  wh + OFF_QR, wl + OFF_QR, qR, nullptr, nullptr, MS, H_ * DHR, DLAT);
    gemm(cKVh, cKVl, wh + OFF_UK, wl + OFF_UK, kC, nullptr, nullptr, MS, D_, DLAT);
    gemm(cKVh, cKVl, wh + OFF_UV, wl + OFF_UV, nullptr, vh, vl, MS, D_, DLAT);
    // assemble q/k (RoPE) -> bf16 hi/lo
    assemble_qk<<<dim3(B_ * H_ * S_ / 4, 2), dim3(256)>>>(qC, qR, kC, kR, qh, ql, kh, kl);
    // flash attention
    flash_mma<<<dim3(S_ / FBQ, B_ * H_), dim3(128), FLASH_SMEM_BYTES>>>(
        qh, ql, kh, kl, vh, vl, ah, al);
    // output projection -> fp32 out
    gemm(ah, al, wh + OFF_WO, wl + OFF_WO, out, nullptr, nullptr, MS, D_, D_);
}

// round 5
// speedup vs baseline: 1.9594x; 1.1502x over previous
#include <cuda_runtime.h>
#include <cuda_bf16.h>
#include <math.h>
#include <stdint.h>

// ---------------- problem constants ----------------
#define B_    4
#define S_    2048
#define D_    1024
#define H_    16
#define DH    64
#define DHR   32
#define DLAT  512
#define MS    (B_*S_)
#define DQK   96

typedef uint32_t u32;
typedef uint64_t u64;
typedef unsigned short u16;

// ---------------- weight pack offsets (elements) ----------------
#define OFF_DQ   0
#define OFF_UQ   524288
#define OFF_QR   1048576
#define OFF_DKV  1310720
#define OFF_UK   1835008
#define OFF_UV   2359296
#define OFF_KR   2883584
#define OFF_WO   2916352
#define WTOT     3964928

// ---------------- scratch (device globals; no allocation) -------
__device__ __align__(16) u16 g_xh [MS*D_],  g_xl [MS*D_];
__device__ __align__(16) u16 g_wh [WTOT],   g_wl [WTOT];
__device__ __align__(16) u16 g_cQh[MS*DLAT],g_cQl[MS*DLAT];
__device__ __align__(16) u16 g_cKVh[MS*DLAT],g_cKVl[MS*DLAT];
__device__ __align__(16) float g_qC[MS*D_];
__device__ __align__(16) float g_qR[MS*H_*DHR];
__device__ __align__(16) float g_kC[MS*D_];
__device__ __align__(16) float g_kR[MS*DHR];
__device__ __align__(16) u16 g_vh [MS*D_],  g_vl [MS*D_];
__device__ __align__(16) u16 g_qh [(size_t)B_*H_*S_*DQK], g_ql[(size_t)B_*H_*S_*DQK];
__device__ __align__(16) u16 g_kh [(size_t)B_*H_*S_*DQK], g_kl[(size_t)B_*H_*S_*DQK];
__device__ __align__(16) u16 g_ah [MS*D_],  g_al [MS*D_];

// ---------------- helpers ----------------
__device__ __forceinline__ unsigned sptr(const void* p) {
    return (unsigned)__cvta_generic_to_shared(p);
}
__device__ __forceinline__ void ldmx4(u32* r, unsigned a) {
    asm volatile("ldmatrix.sync.aligned.m8n8.x4.shared.b16 {%0,%1,%2,%3},[%4];"
        : "=r"(r[0]), "=r"(r[1]), "=r"(r[2]), "=r"(r[3]) : "r"(a));
}
__device__ __forceinline__ void ldmx4t(u32* r, unsigned a) {
    asm volatile("ldmatrix.sync.aligned.m8n8.x4.trans.shared.b16 {%0,%1,%2,%3},[%4];"
        : "=r"(r[0]), "=r"(r[1]), "=r"(r[2]), "=r"(r[3]) : "r"(a));
}
__device__ __forceinline__ void mma16816(float* c, const u32* a, u32 b0, u32 b1) {
    asm volatile("mma.sync.aligned.m16n8k16.row.col.f32.bf16.bf16.f32 "
        "{%0,%1,%2,%3},{%4,%5,%6,%7},{%8,%9},{%0,%1,%2,%3};"
        : "+f"(c[0]), "+f"(c[1]), "+f"(c[2]), "+f"(c[3])
        : "r"(a[0]), "r"(a[1]), "r"(a[2]), "r"(a[3]), "r"(b0), "r"(b1));
}
__device__ __forceinline__ void split_pack(float a, float b, u32& hi, u32& lo) {
    __nv_bfloat16 ha = __float2bfloat16(a), hb = __float2bfloat16(b);
    __nv_bfloat162 hh; hh.x = ha; hh.y = hb;
    hi = *(u32*)&hh;
    __nv_bfloat162 ll;
    ll.x = __float2bfloat16(a - __bfloat162float(ha));
    ll.y = __float2bfloat16(b - __bfloat162float(hb));
    lo = *(u32*)&ll;
}
__device__ __forceinline__ void wsplit(u16* hp, u16* lp, size_t idx, float v) {
    __nv_bfloat16 h = __float2bfloat16(v);
    hp[idx] = *(u16*)&h;
    __nv_bfloat16 l = __float2bfloat16(v - __bfloat162float(h));
    lp[idx] = *(u16*)&l;
}
// cp.async 16B (sm_80+)
__device__ __forceinline__ void cpa16(u32 d, const void* s) {
    asm volatile("cp.async.ca.shared.global [%0], [%1], 16;" :: "r"(d), "l"(s));
}
__device__ __forceinline__ void cpa16z(u32 d, const void* s, int sz) {
    asm volatile("cp.async.ca.shared.global [%0], [%1], 16, %2;"
                 :: "r"(d), "l"(s), "r"(sz));
}
__device__ __forceinline__ void cp_commit() {
    asm volatile("cp.async.commit_group;" ::: "memory");
}

// ---------------- fp32 -> bf16 hi/lo split kernel ----------------
__global__ __launch_bounds__(256) void splitk(
    const float* __restrict__ in, u16* __restrict__ hi, u16* __restrict__ lo, int n4)
{
    int i = blockIdx.x * 256 + threadIdx.x;
    if (i >= n4) return;
    float4 v = ((const float4*)in)[i];
    u32 h0, l0, h1, l1;
    split_pack(v.x, v.y, h0, l0);
    split_pack(v.z, v.w, h1, l1);
    ((uint2*)hi)[i] = make_uint2(h0, h1);
    ((uint2*)lo)[i] = make_uint2(l0, l1);
}

// ---------------- split-bf16 GEMM with cp.async pipeline ----------------
// C[M,N] = A[M,K] * B[N,K]^T; A,B bf16 hi/lo; out fp32 or bf16 hi/lo.
#define GBM 128
#define GBN 128
#define GBK 32
#define GP  40                       // padded row stride (u16)
#define GT  (GBM*GP)                 // one tile (u16 elems)
#define GSTAGE (4*GT)                // Ah,Al,Bh,Bl per stage
#define GEMM_DSMEM (2*GSTAGE*2)      // bytes (81920)

__global__ __launch_bounds__(256) void gemm_cp(
    const u16* __restrict__ Ah, const u16* __restrict__ Al,
    const u16* __restrict__ Bh, const u16* __restrict__ Bl,
    float* __restrict__ Cf, u16* __restrict__ Ch, u16* __restrict__ Cl,
    int M, int N, int K)
{
    extern __shared__ __align__(16) u16 gsm[];
    const int tid = threadIdx.x, lane = tid & 31, wid = tid >> 5;
    const int bm = blockIdx.y * GBM, bn = blockIdx.x * GBN;
    const int wm = (wid & 3) * 32, wn = (wid >> 2) * 64;
    const int g = lane >> 2, t = lane & 3;
    const int nst = K / GBK;

    float acc[2][8][4];
    #pragma unroll
    for (int mi = 0; mi < 2; mi++)
        #pragma unroll
        for (int nj = 0; nj < 8; nj++)
            #pragma unroll
            for (int c = 0; c < 4; c++) acc[mi][nj][c] = 0.f;

    auto load_stage = [&](int s) {
        u16* sb = gsm + (s & 1) * GSTAGE;
        const int k0 = s * GBK;
        #pragma unroll
        for (int i = tid; i < 512; i += 256) {
            int r = i >> 2, c = i & 3;
            int so = r * GP + c * 8;
            size_t ga = (size_t)(bm + r) * K + k0 + c * 8;
            cpa16(sptr(sb + so),      Ah + ga);
            cpa16(sptr(sb + GT + so), Al + ga);
            int br = bn + r;
            int ok = (br < N) ? 16 : 0;
            size_t gb = (size_t)(ok ? br : 0) * K + k0 + c * 8;
            cpa16z(sptr(sb + 2*GT + so), Bh + gb, ok);
            cpa16z(sptr(sb + 3*GT + so), Bl + gb, ok);
        }
        cp_commit();
    };

    load_stage(0);
    if (nst > 1) load_stage(1);

    for (int s = 0; s < nst; s++) {
        if (s + 1 < nst) asm volatile("cp.async.wait_group 1;" ::: "memory");
        else             asm volatile("cp.async.wait_group 0;" ::: "memory");
        __syncthreads();

        u16* sb = gsm + (s & 1) * GSTAGE;
        #pragma unroll
        for (int kk = 0; kk < GBK; kk += 16) {
            u32 a[2][2][4];
            #pragma unroll
            for (int mi = 0; mi < 2; mi++) {
                int row = wm + mi * 16 + (lane & 15), col = kk + (lane >> 4) * 8;
                ldmx4(a[0][mi], sptr(sb + row*GP + col));
                ldmx4(a[1][mi], sptr(sb + GT + row*GP + col));
            }
            #pragma unroll
            for (int ng = 0; ng < 4; ng++) {
                u32 b0[4], b1[4];
                int row = wn + ng * 16 + (lane & 15), col = kk + (lane >> 4) * 8;
                ldmx4(b0, sptr(sb + 2*GT + row*GP + col));
                ldmx4(b1, sptr(sb + 3*GT + row*GP + col));
                #pragma unroll
                for (int mi = 0; mi < 2; mi++) {
                    mma16816(acc[mi][2*ng],   a[0][mi], b0[0], b0[2]);
                    mma16816(acc[mi][2*ng],   a[0][mi], b1[0], b1[2]);
                    mma16816(acc[mi][2*ng],   a[1][mi], b0[0], b0[2]);
                    mma16816(acc[mi][2*ng+1], a[0][mi], b0[1], b0[3]);
                    mma16816(acc[mi][2*ng+1], a[0][mi], b1[1], b1[3]);
                    mma16816(acc[mi][2*ng+1], a[1][mi], b0[1], b0[3]);
                }
            }
        }
        __syncthreads();
        if (s + 2 < nst) load_stage(s + 2);
    }

    #pragma unroll
    for (int mi = 0; mi < 2; mi++) {
        int r0 = bm + wm + mi * 16 + g;
        #pragma unroll
        for (int nj = 0; nj < 8; nj++) {
            int col = bn + wn + nj * 8 + t * 2;
            if (col >= N) continue;
            if (Cf) {
                *(float2*)&Cf[(size_t)r0 * N + col] =
                    make_float2(acc[mi][nj][0], acc[mi][nj][1]);
                *(float2*)&Cf[(size_t)(r0+8) * N + col] =
                    make_float2(acc[mi][nj][2], acc[mi][nj][3]);
            } else {
                u32 h0, l0, h1, l1;
                split_pack(acc[mi][nj][0], acc[mi][nj][1], h0, l0);
                split_pack(acc[mi][nj][2], acc[mi][nj][3], h1, l1);
                *(u32*)&Ch[(size_t)r0 * N + col] = h0;
                *(u32*)&Cl[(size_t)r0 * N + col] = l0;
                *(u32*)&Ch[(size_t)(r0+8) * N + col] = h1;
                *(u32*)&Cl[(size_t)(r0+8) * N + col] = l1;
            }
        }
    }
}

// ---------------- assemble q/k with RoPE -> bf16 hi/lo ----------------
__global__ __launch_bounds__(256) void assemble_qk(
    const float* __restrict__ qc, const float* __restrict__ qr,
    const float* __restrict__ kc, const float* __restrict__ kr,
    u16* __restrict__ qhA, u16* __restrict__ qlA,
    u16* __restrict__ khA, u16* __restrict__ klA)
{
    const int sub = threadIdx.x >> 6;
    const int t   = threadIdx.x & 63;
    const int idx = blockIdx.x * 4 + sub;
    const int s = idx % S_;
    const int h = (idx / S_) % H_;
    const int b = idx / (S_ * H_);
    const bool isK = (blockIdx.y != 0);

    const size_t bs = (size_t)(b * S_ + s);
    u16* hp = isK ? khA : qhA;
    u16* lp = isK ? klA : qlA;
    const size_t base = (size_t)idx * DQK;

    const float* Cpart = isK ? kc : qc;
    wsplit(hp, lp, base + t, Cpart[bs * D_ + h * DH + t]);

    if (t < 16) {
        float x1, x2;
        if (isK) {
            x1 = kr[bs * DHR + 2 * t];
            x2 = kr[bs * DHR + 2 * t + 1];
        } else {
            x1 = qr[bs * (H_ * DHR) + h * DHR + 2 * t];
            x2 = qr[bs * (H_ * DHR) + h * DHR + 2 * t + 1];
        }
        double inv = pow(10000.0, -(double)(2 * t) / (double)DHR);
        double ang = (double)s * inv;
        float c  = (float)cos(ang);
        float sn = (float)sin(ang);
        wsplit(hp, lp, base + DH + 2 * t,     x1 * c  - x2 * sn);
        wsplit(hp, lp, base + DH + 2 * t + 1, x1 * sn + x2 * c);
    }
}

// ---------------- flash attention, split-bf16 HMMA, 128-row q tiles --------
#define FBQ 128
#define FBK 64
#define QKP 104
#define VP  72
// smem (u16): Qh/Ql 128*QKP each, Kh/Kl 64*QKP each, Vh/Vl 64*VP each
#define FQ_OFF  0
#define FK_OFF  (2*128*QKP)
#define FV_OFF  (FK_OFF + 2*64*QKP)
#define FLASH_SMEM_U16 (FV_OFF + 2*64*VP)
#define FLASH_SMEM_BYTES (FLASH_SMEM_U16 * 2)

__global__ __launch_bounds__(256) void flash_mma(
    const u16* __restrict__ Qh, const u16* __restrict__ Ql,
    const u16* __restrict__ Kh, const u16* __restrict__ Kl,
    const u16* __restrict__ Vh, const u16* __restrict__ Vl,
    u16* __restrict__ Oh, u16* __restrict__ Ol)
{
    extern __shared__ __align__(16) u16 smf[];
    u16* Qsh = smf + FQ_OFF;
    u16* Qsl = smf + FQ_OFF + 128*QKP;
    u16* Ksh = smf + FK_OFF;
    u16* Ksl = smf + FK_OFF + 64*QKP;
    u16* Vsh = smf + FV_OFF;
    u16* Vsl = smf + FV_OFF + 64*VP;

    const int bh = blockIdx.y, b = bh / H_, h = bh % H_;
    const int qb = gridDim.x - 1 - blockIdx.x;      // heavy tiles first
    const int q0 = qb * FBQ;
    const int tid = threadIdx.x, w = tid >> 5, lane = tid & 31;
    const int g = lane >> 2, t = lane & 3;

    // load Q tile (128 x 96, hi/lo)
    const size_t qbase = ((size_t)bh * S_ + q0) * DQK;
    #pragma unroll
    for (int c = tid; c < 128 * 12; c += 256) {
        int r = c / 12, s = c % 12;
        *(uint4*)&Qsh[r*QKP + s*8] = *(const uint4*)&Qh[qbase + (size_t)r*DQK + s*8];
        *(uint4*)&Qsl[r*QKP + s*8] = *(const uint4*)&Ql[qbase + (size_t)r*DQK + s*8];
    }

    float acco[8][4];
    #pragma unroll
    for (int j = 0; j < 8; j++)
        #pragma unroll
        for (int c = 0; c < 4; c++) acco[j][c] = 0.f;
    float mstate[2] = {-INFINITY, -INFINITY};
    float lstate[2] = {0.f, 0.f};
    const float scale = rsqrtf(96.f);
    const int qiA = q0 + w * 16 + g;
    const int qiB = qiA + 8;

    const int nkb = (q0 + FBQ) / FBK;
    for (int kb = 0; kb < nkb; kb++) {
        const int k0 = kb * FBK;
        const size_t kbase = ((size_t)bh * S_ + k0) * DQK;
        #pragma unroll
        for (int c = tid; c < 64 * 12; c += 256) {
            int r = c / 12, s = c % 12;
            *(uint4*)&Ksh[r*QKP + s*8] = *(const uint4*)&Kh[kbase + (size_t)r*DQK + s*8];
            *(uint4*)&Ksl[r*QKP + s*8] = *(const uint4*)&Kl[kbase + (size_t)r*DQK + s*8];
        }
        #pragma unroll
        for (int c = tid; c < 64 * 8; c += 256) {
            int r = c >> 3, s = c & 7;
            size_t gv = ((size_t)(b * S_ + k0 + r)) * D_ + h * DH + s * 8;
            *(uint4*)&Vsh[r*VP + s*8] = *(const uint4*)&Vh[gv];
            *(uint4*)&Vsl[r*VP + s*8] = *(const uint4*)&Vl[gv];
        }
        __syncthreads();

        // warp-level early-out: tile entirely above the causal diagonal
        const bool active = (k0 <= q0 + w * 16 + 15);
        if (active) {
            float sc[8][4];
            #pragma unroll
            for (int j = 0; j < 8; j++)
                #pragma unroll
                for (int c = 0; c < 4; c++) sc[j][c] = 0.f;

            #pragma unroll
            for (int kc = 0; kc < 6; kc++) {
                u32 ah[4], al[4];
                {
                    int row = w * 16 + (lane & 15), col = kc * 16 + (lane >> 4) * 8;
                    ldmx4(ah, sptr(&Qsh[row*QKP + col]));
                    ldmx4(al, sptr(&Qsl[row*QKP + col]));
                }
                #pragma unroll
                for (int ng = 0; ng < 4; ng++) {
                    u32 b0[4], b1[4];
                    int row = ng * 16 + (lane & 15), col = kc * 16 + (lane >> 4) * 8;
                    ldmx4(b0, sptr(&Ksh[row*QKP + col]));
                    ldmx4(b1, sptr(&Ksl[row*QKP + col]));
                    mma16816(sc[2*ng],   ah, b0[0], b0[2]);
                    mma16816(sc[2*ng],   ah, b1[0], b1[2]);
                    mma16816(sc[2*ng],   al, b0[0], b0[2]);
                    mma16816(sc[2*ng+1], ah, b0[1], b0[3]);
                    mma16816(sc[2*ng+1], ah, b1[1], b1[3]);
                    mma16816(sc[2*ng+1], al, b0[1], b0[3]);
                }
            }

            const bool diag = (k0 + FBK - 1 > q0 + w * 16);
            #pragma unroll
            for (int j = 0; j < 8; j++) {
                int kcol = k0 + j * 8 + t * 2;
                #pragma unroll
                for (int c = 0; c < 4; c++) {
                    int ki = kcol + (c & 1);
                    int qi = (c < 2) ? qiA : qiB;
                    float v = fminf(fmaxf(sc[j][c], -80.f), 80.f) * scale;
                    sc[j][c] = (!diag || ki <= qi) ? v : -INFINITY;
                }
            }

            float mA = -INFINITY, mB = -INFINITY;
            #pragma unroll
            for (int j = 0; j < 8; j++) {
                mA = fmaxf(mA, fmaxf(sc[j][0], sc[j][1]));
                mB = fmaxf(mB, fmaxf(sc[j][2], sc[j][3]));
            }
            mA = fmaxf(mA, __shfl_xor_sync(0xffffffffu, mA, 1));
            mA = fmaxf(mA, __shfl_xor_sync(0xffffffffu, mA, 2));
            mB = fmaxf(mB, __shfl_xor_sync(0xffffffffu, mB, 1));
            mB = fmaxf(mB, __shfl_xor_sync(0xffffffffu, mB, 2));
            float mnA = fmaxf(mstate[0], mA), mnB = fmaxf(mstate[1], mB);
            float corrA = __expf(mstate[0] - mnA);
            float corrB = __expf(mstate[1] - mnB);
            float sumA = 0.f, sumB = 0.f;
            #pragma unroll
            for (int j = 0; j < 8; j++) {
                sc[j][0] = __expf(sc[j][0] - mnA); sumA += sc[j][0];
                sc[j][1] = __expf(sc[j][1] - mnA); sumA += sc[j][1];
                sc[j][2] = __expf(sc[j][2] - mnB); sumB += sc[j][2];
                sc[j][3] = __expf(sc[j][3] - mnB); sumB += sc[j][3];
            }
            sumA += __shfl_xor_sync(0xffffffffu, sumA, 1);
            sumA += __shfl_xor_sync(0xffffffffu, sumA, 2);
            sumB += __shfl_xor_sync(0xffffffffu, sumB, 1);
            sumB += __shfl_xor_sync(0xffffffffu, sumB, 2);
            lstate[0] = lstate[0] * corrA + sumA;
            lstate[1] = lstate[1] * corrB + sumB;
            mstate[0] = mnA; mstate[1] = mnB;
            #pragma unroll
            for (int vj = 0; vj < 8; vj++) {
                acco[vj][0] *= corrA; acco[vj][1] *= corrA;
                acco[vj][2] *= corrB; acco[vj][3] *= corrB;
            }

            #pragma unroll
            for (int kcp = 0; kcp < 4; kcp++) {
                u32 ph[4], pl[4];
                split_pack(sc[2*kcp  ][0], sc[2*kcp  ][1], ph[0], pl[0]);
                split_pack(sc[2*kcp  ][2], sc[2*kcp  ][3], ph[1], pl[1]);
                split_pack(sc[2*kcp+1][0], sc[2*kcp+1][1], ph[2], pl[2]);
                split_pack(sc[2*kcp+1][2], sc[2*kcp+1][3], ph[3], pl[3]);
                #pragma unroll
                for (int vg = 0; vg < 4; vg++) {
                    u32 v0[4], v1[4];
                    int row = kcp * 16 + (lane & 15), col = vg * 16 + (lane >> 4) * 8;
                    ldmx4t(v0, sptr(&Vsh[row*VP + col]));
                    ldmx4t(v1, sptr(&Vsl[row*VP + col]));
                    mma16816(acco[2*vg],   ph, v0[0], v0[1]);
                    mma16816(acco[2*vg],   ph, v1[0], v1[1]);
                    mma16816(acco[2*vg],   pl, v0[0], v0[1]);
                    mma16816(acco[2*vg+1], ph, v0[2], v0[3]);
                    mma16816(acco[2*vg+1], ph, v1[2], v1[3]);
                    mma16816(acco[2*vg+1], pl, v0[2], v0[3]);
                }
            }
        }
        __syncthreads();
    }

    float ilA = 1.f / lstate[0], ilB = 1.f / lstate[1];
    int rA = b * S_ + q0 + w * 16 + g;
    #pragma unroll
    for (int vj = 0; vj < 8; vj++) {
        int col = h * DH + vj * 8 + t * 2;
        u32 h0, l0, h1, l1;
        split_pack(acco[vj][0] * ilA, acco[vj][1] * ilA, h0, l0);
        split_pack(acco[vj][2] * ilB, acco[vj][3] * ilB, h1, l1);
        *(u32*)&Oh[(size_t)rA * D_ + col] = h0;
        *(u32*)&Ol[(size_t)rA * D_ + col] = l0;
        *(u32*)&Oh[(size_t)(rA+8) * D_ + col] = h1;
        *(u32*)&Ol[(size_t)(rA+8) * D_ + col] = l1;
    }
}

// ---------------- launch ----------------
extern "C" void kernel_launch(void* const* d_in, const int* in_sizes, int n_in,
                              void* d_out, int out_size)
{
    const float* x     = (const float*)d_in[0];
    const float* W_DQ  = (const float*)d_in[1];
    const float* W_UQ  = (const float*)d_in[2];
    const float* W_QR  = (const float*)d_in[3];
    const float* W_DKV = (const float*)d_in[4];
    const float* W_UK  = (const float*)d_in[5];
    const float* W_UV  = (const float*)d_in[6];
    const float* W_KR  = (const float*)d_in[7];
    const float* W_O   = (const float*)d_in[8];
    float* out = (float*)d_out;

    u16 *xh,*xl,*wh,*wl,*cQh,*cQl,*cKVh,*cKVl,*vh,*vl,*qh,*ql,*kh,*kl,*ah,*al;
    float *qC,*qR,*kC,*kR;
    cudaGetSymbolAddress((void**)&xh,  g_xh);   cudaGetSymbolAddress((void**)&xl,  g_xl);
    cudaGetSymbolAddress((void**)&wh,  g_wh);   cudaGetSymbolAddress((void**)&wl,  g_wl);
    cudaGetSymbolAddress((void**)&cQh, g_cQh);  cudaGetSymbolAddress((void**)&cQl, g_cQl);
    cudaGetSymbolAddress((void**)&cKVh,g_cKVh); cudaGetSymbolAddress((void**)&cKVl,g_cKVl);
    cudaGetSymbolAddress((void**)&qC,  g_qC);   cudaGetSymbolAddress((void**)&qR,  g_qR);
    cudaGetSymbolAddress((void**)&kC,  g_kC);   cudaGetSymbolAddress((void**)&kR,  g_kR);
    cudaGetSymbolAddress((void**)&vh,  g_vh);   cudaGetSymbolAddress((void**)&vl,  g_vl);
    cudaGetSymbolAddress((void**)&qh,  g_qh);   cudaGetSymbolAddress((void**)&ql,  g_ql);
    cudaGetSymbolAddress((void**)&kh,  g_kh);   cudaGetSymbolAddress((void**)&kl,  g_kl);
    cudaGetSymbolAddress((void**)&ah,  g_ah);   cudaGetSymbolAddress((void**)&al,  g_al);

    static int configured = 0;
    if (!configured) {
        cudaFuncSetAttribute(flash_mma, cudaFuncAttributeMaxDynamicSharedMemorySize,
                             FLASH_SMEM_BYTES);
        cudaFuncSetAttribute(gemm_cp, cudaFuncAttributeMaxDynamicSharedMemorySize,
                             GEMM_DSMEM);
        configured = 1;
    }

    auto spl = [&](const float* src, u16* dh, u16* dl, int n) {
        int n4 = n / 4;
        splitk<<<(n4 + 255) / 256, 256>>>(src, dh, dl, n4);
    };
    spl(x,     xh,          xl,          MS * D_);
    spl(W_DQ,  wh + OFF_DQ,  wl + OFF_DQ,  DLAT * D_);
    spl(W_UQ,  wh + OFF_UQ,  wl + OFF_UQ,  D_ * DLAT);
    spl(W_QR,  wh + OFF_QR,  wl + OFF_QR,  H_ * DHR * DLAT);
    spl(W_DKV, wh + OFF_DKV, wl + OFF_DKV, DLAT * D_);
    spl(W_UK,  wh + OFF_UK,  wl + OFF_UK,  D_ * DLAT);
    spl(W_UV,  wh + OFF_UV,  wl + OFF_UV,  D_ * DLAT);
    spl(W_KR,  wh + OFF_KR,  wl + OFF_KR,  DHR * D_);
    spl(W_O,   wh + OFF_WO,  wl + OFF_WO,  D_ * D_);

    auto gemm = [&](const u16* Ahp, const u16* Alp, const u16* Bhp, const u16* Blp,
                    float* Cfp, u16* Chp, u16* Clp, int M, int N, int K) {
        gemm_cp<<<dim3((N + GBN - 1) / GBN, M / GBM), 256, GEMM_DSMEM>>>(
            Ahp, Alp, Bhp, Blp, Cfp, Chp, Clp, M, N, K);
    };

    gemm(xh, xl, wh + OFF_DQ,  wl + OFF_DQ,  nullptr, cQh, cQl, MS, DLAT, D_);
    gemm(xh, xl, wh + OFF_DKV, wl + OFF_DKV, nullptr, cKVh, cKVl, MS, DLAT, D_);
    gemm(xh, xl, wh + OFF_KR,  wl + OFF_KR,  kR, nullptr, nullptr, MS, DHR, D_);
    gemm(cQh,  cQl,  wh + OFF_UQ, wl + OFF_UQ, qC, nullptr, nullptr, MS, D_, DLAT);
    gemm(cQh,  cQl,  wh + OFF_QR, wl + OFF_QR, qR, nullptr, nullptr, MS, H_ * DHR, DLAT);
    gemm(cKVh, cKVl, wh + OFF_UK, wl + OFF_UK, kC, nullptr, nullptr, MS, D_, DLAT);
    gemm(cKVh, cKVl, wh + OFF_UV, wl + OFF_UV, nullptr, vh, vl, MS, D_, DLAT);
    assemble_qk<<<dim3(B_ * H_ * S_ / 4, 2), dim3(256)>>>(qC, qR, kC, kR, qh, ql, kh, kl);
    flash_mma<<<dim3(S_ / FBQ, B_ * H_), dim3(256), FLASH_SMEM_BYTES>>>(
        qh, ql, kh, kl, vh, vl, ah, al);
    gemm(ah, al, wh + OFF_WO, wl + OFF_WO, out, nullptr, nullptr, MS, D_, D_);
}

// round 6
// speedup vs baseline: 2.0089x; 1.0253x over previous
#include <cuda_runtime.h>
#include <cuda_bf16.h>
#include <math.h>
#include <stdint.h>

// ---------------- problem constants ----------------
#define B_    4
#define S_    2048
#define D_    1024
#define H_    16
#define DH    64
#define DHR   32
#define DLAT  512
#define MS    (B_*S_)
#define DQK   96

typedef uint32_t u32;
typedef uint64_t u64;
typedef unsigned short u16;

// ---------------- weight pack offsets (elements) ----------------
#define OFF_DQ   0
#define OFF_UQ   524288
#define OFF_QR   1048576
#define OFF_DKV  1310720
#define OFF_UK   1835008
#define OFF_UV   2359296
#define OFF_KR   2883584
#define OFF_WO   2916352
#define WTOT     3964928

// ---------------- scratch (device globals; no allocation) -------
__device__ __align__(16) u16 g_xh [MS*D_],  g_xl [MS*D_];
__device__ __align__(16) u16 g_wh [WTOT],   g_wl [WTOT];
__device__ __align__(16) u16 g_cQh[MS*DLAT],g_cQl[MS*DLAT];
__device__ __align__(16) u16 g_cKVh[MS*DLAT],g_cKVl[MS*DLAT];
__device__ __align__(16) float g_qC[MS*D_];
__device__ __align__(16) float g_qR[MS*H_*DHR];
__device__ __align__(16) float g_kC[MS*D_];
__device__ __align__(16) float g_kR[MS*DHR];
__device__ __align__(16) u16 g_vh [MS*D_],  g_vl [MS*D_];
__device__ __align__(16) u16 g_qh [(size_t)B_*H_*S_*DQK], g_ql[(size_t)B_*H_*S_*DQK];
__device__ __align__(16) u16 g_kh [(size_t)B_*H_*S_*DQK], g_kl[(size_t)B_*H_*S_*DQK];
__device__ __align__(16) u16 g_ah [MS*D_],  g_al [MS*D_];

// ---------------- helpers ----------------
__device__ __forceinline__ unsigned sptr(const void* p) {
    return (unsigned)__cvta_generic_to_shared(p);
}
__device__ __forceinline__ void ldmx4(u32* r, unsigned a) {
    asm volatile("ldmatrix.sync.aligned.m8n8.x4.shared.b16 {%0,%1,%2,%3},[%4];"
        : "=r"(r[0]), "=r"(r[1]), "=r"(r[2]), "=r"(r[3]) : "r"(a));
}
__device__ __forceinline__ void ldmx4t(u32* r, unsigned a) {
    asm volatile("ldmatrix.sync.aligned.m8n8.x4.trans.shared.b16 {%0,%1,%2,%3},[%4];"
        : "=r"(r[0]), "=r"(r[1]), "=r"(r[2]), "=r"(r[3]) : "r"(a));
}
__device__ __forceinline__ void mma16816(float* c, const u32* a, u32 b0, u32 b1) {
    asm volatile("mma.sync.aligned.m16n8k16.row.col.f32.bf16.bf16.f32 "
        "{%0,%1,%2,%3},{%4,%5,%6,%7},{%8,%9},{%0,%1,%2,%3};"
        : "+f"(c[0]), "+f"(c[1]), "+f"(c[2]), "+f"(c[3])
        : "r"(a[0]), "r"(a[1]), "r"(a[2]), "r"(a[3]), "r"(b0), "r"(b1));
}
__device__ __forceinline__ void split_pack(float a, float b, u32& hi, u32& lo) {
    __nv_bfloat16 ha = __float2bfloat16(a), hb = __float2bfloat16(b);
    __nv_bfloat162 hh; hh.x = ha; hh.y = hb;
    hi = *(u32*)&hh;
    __nv_bfloat162 ll;
    ll.x = __float2bfloat16(a - __bfloat162float(ha));
    ll.y = __float2bfloat16(b - __bfloat162float(hb));
    lo = *(u32*)&ll;
}
__device__ __forceinline__ void wsplit(u16* hp, u16* lp, size_t idx, float v) {
    __nv_bfloat16 h = __float2bfloat16(v);
    hp[idx] = *(u16*)&h;
    __nv_bfloat16 l = __float2bfloat16(v - __bfloat162float(h));
    lp[idx] = *(u16*)&l;
}
__device__ __forceinline__ void cpa16(u32 d, const void* s) {
    asm volatile("cp.async.ca.shared.global [%0], [%1], 16;" :: "r"(d), "l"(s));
}
__device__ __forceinline__ void cpa16z(u32 d, const void* s, int sz) {
    asm volatile("cp.async.ca.shared.global [%0], [%1], 16, %2;"
                 :: "r"(d), "l"(s), "r"(sz));
}
__device__ __forceinline__ void cp_commit() {
    asm volatile("cp.async.commit_group;" ::: "memory");
}

// ---------------- merged fp32 -> bf16 hi/lo split (one launch) -------------
#define NSPLIT 9
struct SplitArgs {
    const float* src[NSPLIT];
    u16* dh[NSPLIT];
    u16* dl[NSPLIT];
    int  n4[NSPLIT];
    int  cumblk[NSPLIT + 1];
};

__global__ __launch_bounds__(256) void splitall(SplitArgs a)
{
    int blk = blockIdx.x;
    int r = 0;
    #pragma unroll
    for (int i = 1; i < NSPLIT; i++) if (blk >= a.cumblk[i]) r = i;
    int i4 = (blk - a.cumblk[r]) * 256 + threadIdx.x;
    if (i4 >= a.n4[r]) return;
    float4 v = ((const float4*)a.src[r])[i4];
    u32 h0, l0, h1, l1;
    split_pack(v.x, v.y, h0, l0);
    split_pack(v.z, v.w, h1, l1);
    ((uint2*)a.dh[r])[i4] = make_uint2(h0, h1);
    ((uint2*)a.dl[r])[i4] = make_uint2(l0, l1);
}

// ---------------- split-bf16 GEMM with cp.async pipeline ----------------
#define GBM 128
#define GBN 128
#define GBK 32
#define GP  40
#define GT  (GBM*GP)
#define GSTAGE (4*GT)
#define GEMM_DSMEM (2*GSTAGE*2)

__global__ __launch_bounds__(256, 2) void gemm_cp(
    const u16* __restrict__ Ah, const u16* __restrict__ Al,
    const u16* __restrict__ Bh, const u16* __restrict__ Bl,
    float* __restrict__ Cf, u16* __restrict__ Ch, u16* __restrict__ Cl,
    int M, int N, int K)
{
    extern __shared__ __align__(16) u16 gsm[];
    const int tid = threadIdx.x, lane = tid & 31, wid = tid >> 5;
    const int bm = blockIdx.y * GBM, bn = blockIdx.x * GBN;
    const int wm = (wid & 3) * 32, wn = (wid >> 2) * 64;
    const int g = lane >> 2, t = lane & 3;
    const int nst = K / GBK;

    float acc[2][8][4];
    #pragma unroll
    for (int mi = 0; mi < 2; mi++)
        #pragma unroll
        for (int nj = 0; nj < 8; nj++)
            #pragma unroll
            for (int c = 0; c < 4; c++) acc[mi][nj][c] = 0.f;

    auto load_stage = [&](int s) {
        u16* sb = gsm + (s & 1) * GSTAGE;
        const int k0 = s * GBK;
        #pragma unroll
        for (int i = tid; i < 512; i += 256) {
            int r = i >> 2, c = i & 3;
            int so = r * GP + c * 8;
            size_t ga = (size_t)(bm + r) * K + k0 + c * 8;
            cpa16(sptr(sb + so),      Ah + ga);
            cpa16(sptr(sb + GT + so), Al + ga);
            int br = bn + r;
            int ok = (br < N) ? 16 : 0;
            size_t gb = (size_t)(ok ? br : 0) * K + k0 + c * 8;
            cpa16z(sptr(sb + 2*GT + so), Bh + gb, ok);
            cpa16z(sptr(sb + 3*GT + so), Bl + gb, ok);
        }
        cp_commit();
    };

    load_stage(0);
    if (nst > 1) load_stage(1);

    for (int s = 0; s < nst; s++) {
        if (s + 1 < nst) asm volatile("cp.async.wait_group 1;" ::: "memory");
        else             asm volatile("cp.async.wait_group 0;" ::: "memory");
        __syncthreads();

        u16* sb = gsm + (s & 1) * GSTAGE;
        #pragma unroll
        for (int kk = 0; kk < GBK; kk += 16) {
            u32 a[2][2][4];
            #pragma unroll
            for (int mi = 0; mi < 2; mi++) {
                int row = wm + mi * 16 + (lane & 15), col = kk + (lane >> 4) * 8;
                ldmx4(a[0][mi], sptr(sb + row*GP + col));
                ldmx4(a[1][mi], sptr(sb + GT + row*GP + col));
            }
            #pragma unroll
            for (int ng = 0; ng < 4; ng++) {
                u32 b0[4], b1[4];
                int row = wn + ng * 16 + (lane & 15), col = kk + (lane >> 4) * 8;
                ldmx4(b0, sptr(sb + 2*GT + row*GP + col));
                ldmx4(b1, sptr(sb + 3*GT + row*GP + col));
                #pragma unroll
                for (int mi = 0; mi < 2; mi++) {
                    mma16816(acc[mi][2*ng],   a[0][mi], b0[0], b0[2]);
                    mma16816(acc[mi][2*ng],   a[0][mi], b1[0], b1[2]);
                    mma16816(acc[mi][2*ng],   a[1][mi], b0[0], b0[2]);
                    mma16816(acc[mi][2*ng+1], a[0][mi], b0[1], b0[3]);
                    mma16816(acc[mi][2*ng+1], a[0][mi], b1[1], b1[3]);
                    mma16816(acc[mi][2*ng+1], a[1][mi], b0[1], b0[3]);
                }
            }
        }
        __syncthreads();
        if (s + 2 < nst) load_stage(s + 2);
    }

    #pragma unroll
    for (int mi = 0; mi < 2; mi++) {
        int r0 = bm + wm + mi * 16 + g;
        #pragma unroll
        for (int nj = 0; nj < 8; nj++) {
            int col = bn + wn + nj * 8 + t * 2;
            if (col >= N) continue;
            if (Cf) {
                *(float2*)&Cf[(size_t)r0 * N + col] =
                    make_float2(acc[mi][nj][0], acc[mi][nj][1]);
                *(float2*)&Cf[(size_t)(r0+8) * N + col] =
                    make_float2(acc[mi][nj][2], acc[mi][nj][3]);
            } else {
                u32 h0, l0, h1, l1;
                split_pack(acc[mi][nj][0], acc[mi][nj][1], h0, l0);
                split_pack(acc[mi][nj][2], acc[mi][nj][3], h1, l1);
                *(u32*)&Ch[(size_t)r0 * N + col] = h0;
                *(u32*)&Cl[(size_t)r0 * N + col] = l0;
                *(u32*)&Ch[(size_t)(r0+8) * N + col] = h1;
                *(u32*)&Cl[(size_t)(r0+8) * N + col] = l1;
            }
        }
    }
}

// ---------------- assemble q/k with RoPE -> bf16 hi/lo ----------------
__global__ __launch_bounds__(256) void assemble_qk(
    const float* __restrict__ qc, const float* __restrict__ qr,
    const float* __restrict__ kc, const float* __restrict__ kr,
    u16* __restrict__ qhA, u16* __restrict__ qlA,
    u16* __restrict__ khA, u16* __restrict__ klA)
{
    const int sub = threadIdx.x >> 6;
    const int t   = threadIdx.x & 63;
    const int idx = blockIdx.x * 4 + sub;
    const int s = idx % S_;
    const int h = (idx / S_) % H_;
    const int b = idx / (S_ * H_);
    const bool isK = (blockIdx.y != 0);

    const size_t bs = (size_t)(b * S_ + s);
    u16* hp = isK ? khA : qhA;
    u16* lp = isK ? klA : qlA;
    const size_t base = (size_t)idx * DQK;

    const float* Cpart = isK ? kc : qc;
    wsplit(hp, lp, base + t, Cpart[bs * D_ + h * DH + t]);

    if (t < 16) {
        float x1, x2;
        if (isK) {
            x1 = kr[bs * DHR + 2 * t];
            x2 = kr[bs * DHR + 2 * t + 1];
        } else {
            x1 = qr[bs * (H_ * DHR) + h * DHR + 2 * t];
            x2 = qr[bs * (H_ * DHR) + h * DHR + 2 * t + 1];
        }
        double inv = pow(10000.0, -(double)(2 * t) / (double)DHR);
        double ang = (double)s * inv;
        float c  = (float)cos(ang);
        float sn = (float)sin(ang);
        wsplit(hp, lp, base + DH + 2 * t,     x1 * c  - x2 * sn);
        wsplit(hp, lp, base + DH + 2 * t + 1, x1 * sn + x2 * c);
    }
}

// ---------------- flash attention, cp.async double-buffered K/V ------------
#define FBQ 128
#define FBK 64
#define QKP 104
#define VP  72
#define KVST (2*64*QKP + 2*64*VP)            // u16 per K/V stage
#define FQ_U16 (2*128*QKP)
#define FLASH_SMEM_U16 (FQ_U16 + 2*KVST)
#define FLASH_SMEM_BYTES (FLASH_SMEM_U16 * 2)

__global__ __launch_bounds__(256) void flash_mma(
    const u16* __restrict__ Qh, const u16* __restrict__ Ql,
    const u16* __restrict__ Kh, const u16* __restrict__ Kl,
    const u16* __restrict__ Vh, const u16* __restrict__ Vl,
    u16* __restrict__ Oh, u16* __restrict__ Ol)
{
    extern __shared__ __align__(16) u16 smf[];
    u16* Qsh = smf;
    u16* Qsl = smf + 128*QKP;

    const int bh = blockIdx.y, b = bh / H_, h = bh % H_;
    const int qb = gridDim.x - 1 - blockIdx.x;      // heavy tiles first
    const int q0 = qb * FBQ;
    const int tid = threadIdx.x, w = tid >> 5, lane = tid & 31;
    const int g = lane >> 2, t = lane & 3;

    auto load_kv = [&](int kb) {
        u16* st = smf + FQ_U16 + (kb & 1) * KVST;
        const size_t kbase = ((size_t)bh * S_ + kb * FBK) * DQK;
        #pragma unroll
        for (int c = tid; c < 64 * 12; c += 256) {
            int r = c / 12, s = c % 12;
            const size_t go = kbase + (size_t)r * DQK + s * 8;
            cpa16(sptr(st + r*QKP + s*8),            Kh + go);
            cpa16(sptr(st + 64*QKP + r*QKP + s*8),   Kl + go);
        }
        #pragma unroll
        for (int c = tid; c < 64 * 8; c += 256) {
            int r = c >> 3, s = c & 7;
            size_t gv = ((size_t)(b * S_ + kb * FBK + r)) * D_ + h * DH + s * 8;
            cpa16(sptr(st + 2*64*QKP + r*VP + s*8),          Vh + gv);
            cpa16(sptr(st + 2*64*QKP + 64*VP + r*VP + s*8),  Vl + gv);
        }
        cp_commit();
    };

    // Q load (cp.async, part of group 0) + first K/V stage
    {
        const size_t qbase = ((size_t)bh * S_ + q0) * DQK;
        #pragma unroll
        for (int c = tid; c < 128 * 12; c += 256) {
            int r = c / 12, s = c % 12;
            const size_t go = qbase + (size_t)r * DQK + s * 8;
            cpa16(sptr(Qsh + r*QKP + s*8), Qh + go);
            cpa16(sptr(Qsl + r*QKP + s*8), Ql + go);
        }
        load_kv(0);   // commit: group contains Q + stage 0
    }

    float acco[8][4];
    #pragma unroll
    for (int j = 0; j < 8; j++)
        #pragma unroll
        for (int c = 0; c < 4; c++) acco[j][c] = 0.f;
    float mstate[2] = {-INFINITY, -INFINITY};
    float lstate[2] = {0.f, 0.f};
    const float scale = rsqrtf(96.f);
    const int qiA = q0 + w * 16 + g;
    const int qiB = qiA + 8;

    const int nkb = (q0 + FBQ) / FBK;
    for (int kb = 0; kb < nkb; kb++) {
        if (kb + 1 < nkb) {
            load_kv(kb + 1);
            asm volatile("cp.async.wait_group 1;" ::: "memory");
        } else {
            asm volatile("cp.async.wait_group 0;" ::: "memory");
        }
        __syncthreads();

        u16* st  = smf + FQ_U16 + (kb & 1) * KVST;
        u16* Ksh = st;
        u16* Ksl = st + 64*QKP;
        u16* Vsh = st + 2*64*QKP;
        u16* Vsl = st + 2*64*QKP + 64*VP;
        const int k0 = kb * FBK;

        const bool active = (k0 <= q0 + w * 16 + 15);
        if (active) {
            float sc[8][4];
            #pragma unroll
            for (int j = 0; j < 8; j++)
                #pragma unroll
                for (int c = 0; c < 4; c++) sc[j][c] = 0.f;

            #pragma unroll
            for (int kc = 0; kc < 6; kc++) {
                u32 ah[4], al[4];
                {
                    int row = w * 16 + (lane & 15), col = kc * 16 + (lane >> 4) * 8;
                    ldmx4(ah, sptr(&Qsh[row*QKP + col]));
                    ldmx4(al, sptr(&Qsl[row*QKP + col]));
                }
                #pragma unroll
                for (int ng = 0; ng < 4; ng++) {
                    u32 b0[4], b1[4];
                    int row = ng * 16 + (lane & 15), col = kc * 16 + (lane >> 4) * 8;
                    ldmx4(b0, sptr(&Ksh[row*QKP + col]));
                    ldmx4(b1, sptr(&Ksl[row*QKP + col]));
                    mma16816(sc[2*ng],   ah, b0[0], b0[2]);
                    mma16816(sc[2*ng],   ah, b1[0], b1[2]);
                    mma16816(sc[2*ng],   al, b0[0], b0[2]);
                    mma16816(sc[2*ng+1], ah, b0[1], b0[3]);
                    mma16816(sc[2*ng+1], ah, b1[1], b1[3]);
                    mma16816(sc[2*ng+1], al, b0[1], b0[3]);
                }
            }

            const bool diag = (k0 + FBK - 1 > q0 + w * 16);
            #pragma unroll
            for (int j = 0; j < 8; j++) {
                int kcol = k0 + j * 8 + t * 2;
                #pragma unroll
                for (int c = 0; c < 4; c++) {
                    int ki = kcol + (c & 1);
                    int qi = (c < 2) ? qiA : qiB;
                    float v = fminf(fmaxf(sc[j][c], -80.f), 80.f) * scale;
                    sc[j][c] = (!diag || ki <= qi) ? v : -INFINITY;
                }
            }

            float mA = -INFINITY, mB = -INFINITY;
            #pragma unroll
            for (int j = 0; j < 8; j++) {
                mA = fmaxf(mA, fmaxf(sc[j][0], sc[j][1]));
                mB = fmaxf(mB, fmaxf(sc[j][2], sc[j][3]));
            }
            mA = fmaxf(mA, __shfl_xor_sync(0xffffffffu, mA, 1));
            mA = fmaxf(mA, __shfl_xor_sync(0xffffffffu, mA, 2));
            mB = fmaxf(mB, __shfl_xor_sync(0xffffffffu, mB, 1));
            mB = fmaxf(mB, __shfl_xor_sync(0xffffffffu, mB, 2));
            float mnA = fmaxf(mstate[0], mA), mnB = fmaxf(mstate[1], mB);
            float corrA = __expf(mstate[0] - mnA);
            float corrB = __expf(mstate[1] - mnB);
            float sumA = 0.f, sumB = 0.f;
            #pragma unroll
            for (int j = 0; j < 8; j++) {
                sc[j][0] = __expf(sc[j][0] - mnA); sumA += sc[j][0];
                sc[j][1] = __expf(sc[j][1] - mnA); sumA += sc[j][1];
                sc[j][2] = __expf(sc[j][2] - mnB); sumB += sc[j][2];
                sc[j][3] = __expf(sc[j][3] - mnB); sumB += sc[j][3];
            }
            sumA += __shfl_xor_sync(0xffffffffu, sumA, 1);
            sumA += __shfl_xor_sync(0xffffffffu, sumA, 2);
            sumB += __shfl_xor_sync(0xffffffffu, sumB, 1);
            sumB += __shfl_xor_sync(0xffffffffu, sumB, 2);
            lstate[0] = lstate[0] * corrA + sumA;
            lstate[1] = lstate[1] * corrB + sumB;
            mstate[0] = mnA; mstate[1] = mnB;
            #pragma unroll
            for (int vj = 0; vj < 8; vj++) {
                acco[vj][0] *= corrA; acco[vj][1] *= corrA;
                acco[vj][2] *= corrB; acco[vj][3] *= corrB;
            }

            #pragma unroll
            for (int kcp = 0; kcp < 4; kcp++) {
                u32 ph[4], pl[4];
                split_pack(sc[2*kcp  ][0], sc[2*kcp  ][1], ph[0], pl[0]);
                split_pack(sc[2*kcp  ][2], sc[2*kcp  ][3], ph[1], pl[1]);
                split_pack(sc[2*kcp+1][0], sc[2*kcp+1][1], ph[2], pl[2]);
                split_pack(sc[2*kcp+1][2], sc[2*kcp+1][3], ph[3], pl[3]);
                #pragma unroll
                for (int vg = 0; vg < 4; vg++) {
                    u32 v0[4], v1[4];
                    int row = kcp * 16 + (lane & 15), col = vg * 16 + (lane >> 4) * 8;
                    ldmx4t(v0, sptr(&Vsh[row*VP + col]));
                    ldmx4t(v1, sptr(&Vsl[row*VP + col]));
                    mma16816(acco[2*vg],   ph, v0[0], v0[1]);
                    mma16816(acco[2*vg],   ph, v1[0], v1[1]);
                    mma16816(acco[2*vg],   pl, v0[0], v0[1]);
                    mma16816(acco[2*vg+1], ph, v0[2], v0[3]);
                    mma16816(acco[2*vg+1], ph, v1[2], v1[3]);
                    mma16816(acco[2*vg+1], pl, v0[2], v0[3]);
                }
            }
        }
        __syncthreads();
    }

    float ilA = 1.f / lstate[0], ilB = 1.f / lstate[1];
    int rA = b * S_ + q0 + w * 16 + g;
    #pragma unroll
    for (int vj = 0; vj < 8; vj++) {
        int col = h * DH + vj * 8 + t * 2;
        u32 h0, l0, h1, l1;
        split_pack(acco[vj][0] * ilA, acco[vj][1] * ilA, h0, l0);
        split_pack(acco[vj][2] * ilB, acco[vj][3] * ilB, h1, l1);
        *(u32*)&Oh[(size_t)rA * D_ + col] = h0;
        *(u32*)&Ol[(size_t)rA * D_ + col] = l0;
        *(u32*)&Oh[(size_t)(rA+8) * D_ + col] = h1;
        *(u32*)&Ol[(size_t)(rA+8) * D_ + col] = l1;
    }
}

// ---------------- launch ----------------
extern "C" void kernel_launch(void* const* d_in, const int* in_sizes, int n_in,
                              void* d_out, int out_size)
{
    const float* x     = (const float*)d_in[0];
    const float* W_DQ  = (const float*)d_in[1];
    const float* W_UQ  = (const float*)d_in[2];
    const float* W_QR  = (const float*)d_in[3];
    const float* W_DKV = (const float*)d_in[4];
    const float* W_UK  = (const float*)d_in[5];
    const float* W_UV  = (const float*)d_in[6];
    const float* W_KR  = (const float*)d_in[7];
    const float* W_O   = (const float*)d_in[8];
    float* out = (float*)d_out;

    u16 *xh,*xl,*wh,*wl,*cQh,*cQl,*cKVh,*cKVl,*vh,*vl,*qh,*ql,*kh,*kl,*ah,*al;
    float *qC,*qR,*kC,*kR;
    cudaGetSymbolAddress((void**)&xh,  g_xh);   cudaGetSymbolAddress((void**)&xl,  g_xl);
    cudaGetSymbolAddress((void**)&wh,  g_wh);   cudaGetSymbolAddress((void**)&wl,  g_wl);
    cudaGetSymbolAddress((void**)&cQh, g_cQh);  cudaGetSymbolAddress((void**)&cQl, g_cQl);
    cudaGetSymbolAddress((void**)&cKVh,g_cKVh); cudaGetSymbolAddress((void**)&cKVl,g_cKVl);
    cudaGetSymbolAddress((void**)&qC,  g_qC);   cudaGetSymbolAddress((void**)&qR,  g_qR);
    cudaGetSymbolAddress((void**)&kC,  g_kC);   cudaGetSymbolAddress((void**)&kR,  g_kR);
    cudaGetSymbolAddress((void**)&vh,  g_vh);   cudaGetSymbolAddress((void**)&vl,  g_vl);
    cudaGetSymbolAddress((void**)&qh,  g_qh);   cudaGetSymbolAddress((void**)&ql,  g_ql);
    cudaGetSymbolAddress((void**)&kh,  g_kh);   cudaGetSymbolAddress((void**)&kl,  g_kl);
    cudaGetSymbolAddress((void**)&ah,  g_ah);   cudaGetSymbolAddress((void**)&al,  g_al);

    static int configured = 0;
    if (!configured) {
        cudaFuncSetAttribute(flash_mma, cudaFuncAttributeMaxDynamicSharedMemorySize,
                             FLASH_SMEM_BYTES);
        cudaFuncSetAttribute(gemm_cp, cudaFuncAttributeMaxDynamicSharedMemorySize,
                             GEMM_DSMEM);
        configured = 1;
    }

    // ---- launch 0: merged split of all fp32 inputs ----
    SplitArgs sa;
    const float* srcs[NSPLIT] = {x, W_DQ, W_UQ, W_QR, W_DKV, W_UK, W_UV, W_KR, W_O};
    u16* dhs[NSPLIT] = {xh, wh+OFF_DQ, wh+OFF_UQ, wh+OFF_QR, wh+OFF_DKV,
                        wh+OFF_UK, wh+OFF_UV, wh+OFF_KR, wh+OFF_WO};
    u16* dls[NSPLIT] = {xl, wl+OFF_DQ, wl+OFF_UQ, wl+OFF_QR, wl+OFF_DKV,
                        wl+OFF_UK, wl+OFF_UV, wl+OFF_KR, wl+OFF_WO};
    const int ns[NSPLIT] = {MS*D_, DLAT*D_, D_*DLAT, H_*DHR*DLAT, DLAT*D_,
                            D_*DLAT, D_*DLAT, DHR*D_, D_*D_};
    int cum = 0;
    for (int i = 0; i < NSPLIT; i++) {
        sa.src[i] = srcs[i]; sa.dh[i] = dhs[i]; sa.dl[i] = dls[i];
        sa.n4[i] = ns[i] / 4;
        sa.cumblk[i] = cum;
        cum += (sa.n4[i] + 255) / 256;
    }
    sa.cumblk[NSPLIT] = cum;
    splitall<<<cum, 256>>>(sa);

    auto gemm = [&](const u16* Ahp, const u16* Alp, const u16* Bhp, const u16* Blp,
                    float* Cfp, u16* Chp, u16* Clp, int M, int N, int K) {
        gemm_cp<<<dim3((N + GBN - 1) / GBN, M / GBM), 256, GEMM_DSMEM>>>(
            Ahp, Alp, Bhp, Blp, Cfp, Chp, Clp, M, N, K);
    };

    // launch order chosen so index 5 (ncu -s 5 -c 1) is the big UK GEMM
    gemm(xh, xl, wh + OFF_DQ,  wl + OFF_DQ,  nullptr, cQh, cQl, MS, DLAT, D_);   // 1
    gemm(xh, xl, wh + OFF_DKV, wl + OFF_DKV, nullptr, cKVh, cKVl, MS, DLAT, D_); // 2
    gemm(xh, xl, wh + OFF_KR,  wl + OFF_KR,  kR, nullptr, nullptr, MS, DHR, D_); // 3
    gemm(cQh,  cQl,  wh + OFF_UQ, wl + OFF_UQ, qC, nullptr, nullptr, MS, D_, DLAT);   // 4
    gemm(cKVh, cKVl, wh + OFF_UK, wl + OFF_UK, kC, nullptr, nullptr, MS, D_, DLAT);   // 5 <- profiled
    gemm(cQh,  cQl,  wh + OFF_QR, wl + OFF_QR, qR, nullptr, nullptr, MS, H_ * DHR, DLAT); // 6
    gemm(cKVh, cKVl, wh + OFF_UV, wl + OFF_UV, nullptr, vh, vl, MS, D_, DLAT);   // 7
    assemble_qk<<<dim3(B_ * H_ * S_ / 4, 2), dim3(256)>>>(qC, qR, kC, kR, qh, ql, kh, kl);
    flash_mma<<<dim3(S_ / FBQ, B_ * H_), dim3(256), FLASH_SMEM_BYTES>>>(
        qh, ql, kh, kl, vh, vl, ah, al);
    gemm(ah, al, wh + OFF_WO, wl + OFF_WO, out, nullptr, nullptr, MS, D_, D_);
}